// round 1
// baseline (speedup 1.0000x reference)
#include <cuda_runtime.h>

#define TT 2048
#define BB 8
#define CC 1024
#define HH 64

// Scratch for projected q, k, v: [B, T, H] each, fp32. 4 MB each.
__device__ float g_q[BB * TT * HH];
__device__ float g_k[BB * TT * HH];
__device__ float g_v[BB * TT * HH];

// ---------------------------------------------------------------------------
// Kernel 1: fused QKV projection.
// GEMM: [16384 x 1024] @ [1024 x 192]  (192 = Hq | Hk | Hv concatenated)
// Tile: 64 rows x 192 cols per block, K in chunks of 16.
// Thread (ty, tx) in 16x16 grid computes rows {ty+16i} x cols {tx+16j},
// i<4, j<12 (strided mapping -> conflict-free smem reads, coalesced writes).
// ---------------------------------------------------------------------------
__global__ __launch_bounds__(256) void proj_kernel(
    const float* __restrict__ x,
    const float* __restrict__ Wq,
    const float* __restrict__ Wk,
    const float* __restrict__ Wv)
{
    __shared__ __align__(16) float xs[64][16];
    __shared__ float ws[16][192];

    const int tid = threadIdx.x;
    const int ty = tid >> 4;
    const int tx = tid & 15;
    const int row0 = blockIdx.x * 64;   // 256 blocks * 64 = 16384 rows

    float acc[4][12];
#pragma unroll
    for (int i = 0; i < 4; i++)
#pragma unroll
        for (int j = 0; j < 12; j++) acc[i][j] = 0.f;

    const int lr = tid >> 2;     // 0..63 : row for x-tile load
    const int lseg = tid & 3;    // 0..3  : 4-float segment

    for (int k0 = 0; k0 < CC; k0 += 16) {
        // x tile: 64 rows x 16 cols, one float4 per thread
        float4 xv = *(const float4*)(x + (size_t)(row0 + lr) * CC + k0 + lseg * 4);
        *(float4*)&xs[lr][lseg * 4] = xv;

        // W tile: 16 x 192 (Wq|Wk|Wv)
        for (int idx = tid; idx < 16 * 192; idx += 256) {
            int kk = idx / 192;
            int h = idx - kk * 192;
            float w;
            if (h < 64)       w = Wq[(k0 + kk) * 64 + h];
            else if (h < 128) w = Wk[(k0 + kk) * 64 + (h - 64)];
            else              w = Wv[(k0 + kk) * 64 + (h - 128)];
            ws[kk][h] = w;
        }
        __syncthreads();

#pragma unroll
        for (int kk = 0; kk < 16; kk++) {
            float a[4], bb[12];
#pragma unroll
            for (int i = 0; i < 4; i++) a[i] = xs[ty + 16 * i][kk];
#pragma unroll
            for (int j = 0; j < 12; j++) bb[j] = ws[kk][tx + 16 * j];
#pragma unroll
            for (int i = 0; i < 4; i++)
#pragma unroll
                for (int j = 0; j < 12; j++)
                    acc[i][j] = fmaf(a[i], bb[j], acc[i][j]);
        }
        __syncthreads();
    }

#pragma unroll
    for (int i = 0; i < 4; i++) {
        int r = row0 + ty + 16 * i;
#pragma unroll
        for (int j = 0; j < 12; j++) {
            int col = tx + 16 * j;
            float v = acc[i][j];
            if (col < 64)       g_q[(size_t)r * 64 + col] = v;
            else if (col < 128) g_k[(size_t)r * 64 + (col - 64)] = v;
            else                g_v[(size_t)r * 64 + (col - 128)] = v;
        }
    }
}

// ---------------------------------------------------------------------------
// Kernel 2: flash attention with resonance bias/mask.
// Block = (batch, 64-query tile). Streams 32-key tiles with online softmax.
// Mask derived from rbias: allowed(qi,kj) = (kj<=qi) && (rbias>0 || kj==qi).
// smem: 42.5 KB (static, <48 KB).
// ---------------------------------------------------------------------------
__global__ __launch_bounds__(256) void attn_kernel(
    const float* __restrict__ rbias,
    float* __restrict__ out)
{
    __shared__ float qs[64 * 65];   // [64 rows][64 h] pitch 65
    __shared__ float ks[32 * 65];   // [32 keys][64 h] pitch 65
    __shared__ float vs[32 * 65];   // [32 keys][64 h] pitch 65
    __shared__ float ss[64 * 33];   // [64 rows][32 keys] pitch 33
    __shared__ float m_s[64];
    __shared__ float l_s[64];
    __shared__ float corr[64];

    const int b = blockIdx.y;
    const int qb = 31 - blockIdx.x;     // launch heavy tiles first
    const int q0 = qb * 64;
    const int tid = threadIdx.x;
    const int ty = tid >> 4;
    const int tx = tid & 15;

    // Load Q tile
    for (int idx = tid; idx < 64 * 64; idx += 256) {
        int r = idx >> 6, h = idx & 63;
        qs[r * 65 + h] = g_q[(size_t)(b * TT + q0 + r) * HH + h];
    }
    if (tid < 64) { m_s[tid] = -1e30f; l_s[tid] = 0.f; }

    float o[4][4];
#pragma unroll
    for (int i = 0; i < 4; i++)
#pragma unroll
        for (int j = 0; j < 4; j++) o[i][j] = 0.f;

    const int nkb = 2 * qb + 2;   // key tiles cover [0, q0+64)
    for (int kb = 0; kb < nkb; kb++) {
        const int k0 = kb * 32;

        // Load K, V tiles (32 x 64 each)
        for (int idx = tid; idx < 32 * 64; idx += 256) {
            int r = idx >> 6, h = idx & 63;
            ks[r * 65 + h] = g_k[(size_t)(b * TT + k0 + r) * HH + h];
            vs[r * 65 + h] = g_v[(size_t)(b * TT + k0 + r) * HH + h];
        }
        __syncthreads();

        // S = Q K^T : each thread 4 rows x 2 key-cols
        float acc[4][2];
#pragma unroll
        for (int i = 0; i < 4; i++) { acc[i][0] = 0.f; acc[i][1] = 0.f; }
#pragma unroll
        for (int h = 0; h < 64; h++) {
            float a[4], kk2[2];
#pragma unroll
            for (int i = 0; i < 4; i++) a[i] = qs[(ty + 16 * i) * 65 + h];
#pragma unroll
            for (int j = 0; j < 2; j++) kk2[j] = ks[(tx + 16 * j) * 65 + h];
#pragma unroll
            for (int i = 0; i < 4; i++)
#pragma unroll
                for (int j = 0; j < 2; j++)
                    acc[i][j] = fmaf(a[i], kk2[j], acc[i][j]);
        }

        // scale + bias + mask -> ss
#pragma unroll
        for (int i = 0; i < 4; i++) {
            int qi = q0 + ty + 16 * i;
#pragma unroll
            for (int j = 0; j < 2; j++) {
                int kj = k0 + tx + 16 * j;
                float bias = rbias[qi * TT + kj];
                bool allow = (kj <= qi) && (bias > 0.f || kj == qi);
                float sv = allow ? fmaf(acc[i][j], 0.03125f, bias) : -1e30f;
                ss[(ty + 16 * i) * 33 + tx + 16 * j] = sv;
            }
        }
        __syncthreads();

        // Online softmax update: one thread per row
        if (tid < 64) {
            float m_old = m_s[tid];
            float m_new = m_old;
            float* row = &ss[tid * 33];
#pragma unroll
            for (int c = 0; c < 32; c++) m_new = fmaxf(m_new, row[c]);
            // base clamp: if entire history masked (m_new=-1e30), exp(row-base)->0
            float base = fmaxf(m_new, -1e28f);
            float cr = __expf(m_old - m_new);
            float sum = 0.f;
#pragma unroll
            for (int c = 0; c < 32; c++) {
                float p = __expf(row[c] - base);
                row[c] = p;
                sum += p;
            }
            l_s[tid] = l_s[tid] * cr + sum;
            m_s[tid] = m_new;
            corr[tid] = cr;
        }
        __syncthreads();

        // O = O*corr + P @ V : each thread 4 rows x 4 h-cols
        float cf[4];
#pragma unroll
        for (int i = 0; i < 4; i++) cf[i] = corr[ty + 16 * i];
#pragma unroll
        for (int i = 0; i < 4; i++)
#pragma unroll
            for (int j = 0; j < 4; j++) o[i][j] *= cf[i];
#pragma unroll
        for (int c = 0; c < 32; c++) {
            float p[4], vv[4];
#pragma unroll
            for (int i = 0; i < 4; i++) p[i] = ss[(ty + 16 * i) * 33 + c];
#pragma unroll
            for (int j = 0; j < 4; j++) vv[j] = vs[c * 65 + tx + 16 * j];
#pragma unroll
            for (int i = 0; i < 4; i++)
#pragma unroll
                for (int j = 0; j < 4; j++)
                    o[i][j] = fmaf(p[i], vv[j], o[i][j]);
        }
        __syncthreads();   // protect ks/vs/ss before next tile's loads
    }

    float li[4];
#pragma unroll
    for (int i = 0; i < 4; i++) li[i] = l_s[ty + 16 * i];
#pragma unroll
    for (int i = 0; i < 4; i++) {
        int r = q0 + ty + 16 * i;
        float inv = 1.f / li[i];
#pragma unroll
        for (int j = 0; j < 4; j++) {
            out[(size_t)(b * TT + r) * HH + tx + 16 * j] = o[i][j] * inv;
        }
    }
}

// ---------------------------------------------------------------------------
// Inputs (metadata order): x, Wq, Wk, Wv, rbias, allowed
// Output: [B, T, H] float32
// ---------------------------------------------------------------------------
extern "C" void kernel_launch(void* const* d_in, const int* in_sizes, int n_in,
                              void* d_out, int out_size)
{
    const float* x     = (const float*)d_in[0];
    const float* Wq    = (const float*)d_in[1];
    const float* Wk    = (const float*)d_in[2];
    const float* Wv    = (const float*)d_in[3];
    const float* rbias = (const float*)d_in[4];
    // d_in[5] = allowed: not needed (derived from rbias)
    float* out = (float*)d_out;

    proj_kernel<<<256, 256>>>(x, Wq, Wk, Wv);
    attn_kernel<<<dim3(32, 8), 256>>>(rbias, out);
}

// round 5
// speedup vs baseline: 1.8921x; 1.8921x over previous
#include <cuda_runtime.h>

#define TT 2048
#define BB 8
#define CC 1024
#define HH 64

typedef unsigned long long u64;

// ---- packed fp32x2 helpers (sm_100+ PTX; exact IEEE fp32 semantics) ----
__device__ __forceinline__ u64 pk2(float lo, float hi) {
    u64 r; asm("mov.b64 %0, {%1,%2};" : "=l"(r) : "f"(lo), "f"(hi)); return r;
}
__device__ __forceinline__ u64 pkd(float v) { return pk2(v, v); }
__device__ __forceinline__ void upk(u64 v, float& lo, float& hi) {
    asm("mov.b64 {%0,%1}, %2;" : "=f"(lo), "=f"(hi) : "l"(v));
}
__device__ __forceinline__ u64 fma2(u64 a, u64 b, u64 c) {
    u64 d; asm("fma.rn.f32x2 %0, %1, %2, %3;" : "=l"(d) : "l"(a), "l"(b), "l"(c)); return d;
}
__device__ __forceinline__ u64 mul2(u64 a, u64 b) {
    u64 d; asm("mul.rn.f32x2 %0, %1, %2;" : "=l"(d) : "l"(a), "l"(b)); return d;
}

// Scratch for projected q, k, v: [B, T, H] each, fp32. 4 MB each.
__device__ float g_q[BB * TT * HH];
__device__ float g_k[BB * TT * HH];
__device__ float g_v[BB * TT * HH];

// ---------------------------------------------------------------------------
// Kernel 1: fused QKV projection.  [16384 x 1024] @ [1024 x 192]
// Block: 64 rows x 192 cols, k-chunk 16, register-prefetch double buffering.
// Thread (g, tx): rows g*4..+3, cols tx*12..+11, FFMA2-packed accumulators.
// ---------------------------------------------------------------------------
__global__ __launch_bounds__(256) void proj_kernel(
    const float* __restrict__ x,
    const float* __restrict__ Wq,
    const float* __restrict__ Wk,
    const float* __restrict__ Wv)
{
    __shared__ __align__(16) float xs[16][68];    // [kk][row]  (transposed)
    __shared__ __align__(16) float ws[16][196];   // [kk][col 0..191]

    const int tid = threadIdx.x;
    const int g = tid >> 4;          // 0..15
    const int tx = tid & 15;         // 0..15
    const int R = g * 4;             // row base within tile
    const int c0 = tx * 12;          // col base
    const int row0 = blockIdx.x * 64;

    u64 acc[4][6];
#pragma unroll
    for (int i = 0; i < 4; i++)
#pragma unroll
        for (int j = 0; j < 6; j++) acc[i][j] = 0ull;

    // x-tile load mapping: 1 float4/thread
    const int xr = tid >> 2;                 // 0..63
    const int xseg = (tid & 3) * 4;          // 0,4,8,12
    const float* xp = x + (size_t)(row0 + xr) * CC + xseg;

    // W-tile load mapping: 3 float4/thread over 16x192
    int wkk[3], wh[3];
    const float* wp[3];
#pragma unroll
    for (int i = 0; i < 3; i++) {
        int idx4 = tid + 256 * i;            // < 768
        wkk[i] = idx4 / 48;
        wh[i] = 4 * (idx4 - 48 * wkk[i]);    // 0..188
        int h = wh[i];
        wp[i] = (h < 64) ? (Wq + h) : (h < 128) ? (Wk + (h - 64)) : (Wv + (h - 128));
    }

    // prefetch chunk 0
    float4 xv = *(const float4*)(xp);
    float4 wv[3];
#pragma unroll
    for (int i = 0; i < 3; i++)
        wv[i] = *(const float4*)(wp[i] + (size_t)wkk[i] * 64);

    for (int k0 = 0; k0 < CC; k0 += 16) {
        // store prefetched tile
        xs[xseg + 0][xr] = xv.x;
        xs[xseg + 1][xr] = xv.y;
        xs[xseg + 2][xr] = xv.z;
        xs[xseg + 3][xr] = xv.w;
#pragma unroll
        for (int i = 0; i < 3; i++)
            *(float4*)&ws[wkk[i]][wh[i]] = wv[i];
        __syncthreads();

        // prefetch next chunk (overlaps compute)
        if (k0 + 16 < CC) {
            xv = *(const float4*)(xp + k0 + 16);
#pragma unroll
            for (int i = 0; i < 3; i++)
                wv[i] = *(const float4*)(wp[i] + (size_t)(k0 + 16 + wkk[i]) * 64);
        }

#pragma unroll
        for (int kk = 0; kk < 16; kk++) {
            float4 a = *(const float4*)&xs[kk][R];
            u64 a0 = pkd(a.x), a1 = pkd(a.y), a2 = pkd(a.z), a3 = pkd(a.w);
            const u64* bp = (const u64*)&ws[kk][c0];
#pragma unroll
            for (int j = 0; j < 6; j++) {
                u64 b = bp[j];
                acc[0][j] = fma2(a0, b, acc[0][j]);
                acc[1][j] = fma2(a1, b, acc[1][j]);
                acc[2][j] = fma2(a2, b, acc[2][j]);
                acc[3][j] = fma2(a3, b, acc[3][j]);
            }
        }
        __syncthreads();
    }

    // epilogue: even column pairs never straddle the 64-aligned q/k/v segments
#pragma unroll
    for (int i = 0; i < 4; i++) {
        size_t r = (size_t)(row0 + R + i);
#pragma unroll
        for (int j = 0; j < 6; j++) {
            float lo, hi; upk(acc[i][j], lo, hi);
            int cc = c0 + 2 * j;
            int seg = cc >> 6, off = cc & 63;
            float* base = (seg == 0) ? g_q : (seg == 1) ? g_k : g_v;
            float2 val; val.x = lo; val.y = hi;
            *(float2*)&base[r * 64 + off] = val;
        }
    }
}

// ---------------------------------------------------------------------------
// Kernel 2: flash attention with resonance bias/mask (derived from rbias).
// Block = (batch, 32-query tile), 128 threads, 32-key tiles, online softmax
// parallelized 4 threads/row. FFMA2-packed S and PV phases. smem ~31 KB.
// ---------------------------------------------------------------------------
__global__ __launch_bounds__(128) void attn_kernel(
    const float* __restrict__ rbias,
    float* __restrict__ out)
{
    __shared__ __align__(16) float qs[64][36];   // [h][row]
    __shared__ __align__(16) float ks[64][34];   // [h][key]
    __shared__ __align__(16) float vs[32][68];   // [key][h]
    __shared__ __align__(16) float ss[32][34];   // [row][key]
    __shared__ float m_s[32], l_s[32], corr[32];

    const int b = blockIdx.y;
    const int qb = 63 - blockIdx.x;      // heavy tiles first
    const int q0 = qb * 32;
    const int tid = threadIdx.x;
    const int g = tid >> 4;              // 0..7
    const int tx = tid & 15;             // 0..15
    const int R = g * 4;                 // S/O row base
    const int c2 = tx * 2;               // S col pair base
    const int c4 = tx * 4;               // PV/O col base

    // Load Q tile (32 x 64) transposed into qs[h][r]
#pragma unroll
    for (int i = 0; i < 4; i++) {
        int idx = tid + 128 * i;            // 0..511
        int r = idx >> 4;
        int hs = (idx & 15) * 4;
        float4 v = *(const float4*)&g_q[((size_t)(b * TT + q0 + r)) * HH + hs];
        qs[hs + 0][r] = v.x; qs[hs + 1][r] = v.y;
        qs[hs + 2][r] = v.z; qs[hs + 3][r] = v.w;
    }
    if (tid < 32) { m_s[tid] = -1e30f; l_s[tid] = 0.f; }

    u64 o[4][2];
#pragma unroll
    for (int i = 0; i < 4; i++) { o[i][0] = 0ull; o[i][1] = 0ull; }

    const int nkb = qb + 1;   // key tiles cover [0, q0+32)
    for (int kb = 0; kb < nkb; kb++) {
        const int k0 = kb * 32;
        __syncthreads();   // prev PV done (also covers initial Q/m/l stores)

        // Load K (transposed) and V (row-major) tiles
#pragma unroll
        for (int i = 0; i < 4; i++) {
            int idx = tid + 128 * i;
            int r = idx >> 4;
            int hs = (idx & 15) * 4;
            size_t gi = ((size_t)(b * TT + k0 + r)) * HH + hs;
            float4 kv = *(const float4*)&g_k[gi];
            ks[hs + 0][r] = kv.x; ks[hs + 1][r] = kv.y;
            ks[hs + 2][r] = kv.z; ks[hs + 3][r] = kv.w;
            float4 vv = *(const float4*)&g_v[gi];
            *(float4*)&vs[r][hs] = vv;
        }
        __syncthreads();

        // S = Q K^T : 4 rows x 2 packed cols per thread
        u64 acc[4] = {0ull, 0ull, 0ull, 0ull};
#pragma unroll
        for (int h = 0; h < 64; h++) {
            float4 a = *(const float4*)&qs[h][R];
            u64 kk2 = *(const u64*)&ks[h][c2];
            acc[0] = fma2(pkd(a.x), kk2, acc[0]);
            acc[1] = fma2(pkd(a.y), kk2, acc[1]);
            acc[2] = fma2(pkd(a.z), kk2, acc[2]);
            acc[3] = fma2(pkd(a.w), kk2, acc[3]);
        }

        // scale + bias + mask -> ss
#pragma unroll
        for (int i = 0; i < 4; i++) {
            int qi = q0 + R + i;
            int kj = k0 + c2;
            float2 bb = *(const float2*)&rbias[(size_t)qi * TT + kj];
            float lo, hi; upk(acc[i], lo, hi);
            bool al0 = (kj <= qi) && (bb.x > 0.f || kj == qi);
            bool al1 = (kj + 1 <= qi) && (bb.y > 0.f || kj + 1 == qi);
            float s0 = al0 ? fmaf(lo, 0.03125f, bb.x) : -1e30f;
            float s1 = al1 ? fmaf(hi, 0.03125f, bb.y) : -1e30f;
            *(u64*)&ss[R + i][c2] = pk2(s0, s1);
        }
        __syncthreads();

        // Online softmax: 4 threads per row via quad shuffles
        {
            int row = tid >> 2, sub = tid & 3;
            float* rp = &ss[row][sub * 8];
            float mx = -1e30f;
#pragma unroll
            for (int c = 0; c < 8; c++) mx = fmaxf(mx, rp[c]);
            mx = fmaxf(mx, __shfl_xor_sync(0xffffffffu, mx, 1));
            mx = fmaxf(mx, __shfl_xor_sync(0xffffffffu, mx, 2));
            float m_old = m_s[row];
            float m_new = fmaxf(m_old, mx);
            float base = fmaxf(m_new, -1e28f);
            float sum = 0.f;
#pragma unroll
            for (int c = 0; c < 8; c++) {
                float p = __expf(rp[c] - base);
                rp[c] = p;
                sum += p;
            }
            sum += __shfl_xor_sync(0xffffffffu, sum, 1);
            sum += __shfl_xor_sync(0xffffffffu, sum, 2);
            if (sub == 0) {
                float cr = __expf(m_old - m_new);
                l_s[row] = l_s[row] * cr + sum;
                m_s[row] = m_new;
                corr[row] = cr;
            }
        }
        __syncthreads();

        // O = O*corr + P @ V : 4 rows x 4 packed cols per thread
        {
            u64 crd[4];
#pragma unroll
            for (int i = 0; i < 4; i++) crd[i] = pkd(corr[R + i]);
#pragma unroll
            for (int i = 0; i < 4; i++) {
                o[i][0] = mul2(o[i][0], crd[i]);
                o[i][1] = mul2(o[i][1], crd[i]);
            }
#pragma unroll
            for (int c = 0; c < 32; c++) {
                ulonglong2 v2 = *(const ulonglong2*)&vs[c][c4];
#pragma unroll
                for (int i = 0; i < 4; i++) {
                    u64 p = pkd(ss[R + i][c]);
                    o[i][0] = fma2(p, v2.x, o[i][0]);
                    o[i][1] = fma2(p, v2.y, o[i][1]);
                }
            }
        }
    }

    // epilogue: normalize and store
#pragma unroll
    for (int i = 0; i < 4; i++) {
        float inv = 1.f / l_s[R + i];
        float a0, a1, a2, a3;
        upk(o[i][0], a0, a1);
        upk(o[i][1], a2, a3);
        float4 ov; ov.x = a0 * inv; ov.y = a1 * inv; ov.z = a2 * inv; ov.w = a3 * inv;
        *(float4*)&out[((size_t)(b * TT + q0 + R + i)) * HH + c4] = ov;
    }
}

// ---------------------------------------------------------------------------
// Inputs (metadata order): x, Wq, Wk, Wv, rbias, allowed
// Output: [B, T, H] float32
// ---------------------------------------------------------------------------
extern "C" void kernel_launch(void* const* d_in, const int* in_sizes, int n_in,
                              void* d_out, int out_size)
{
    const float* x     = (const float*)d_in[0];
    const float* Wq    = (const float*)d_in[1];
    const float* Wk    = (const float*)d_in[2];
    const float* Wv    = (const float*)d_in[3];
    const float* rbias = (const float*)d_in[4];
    // d_in[5] = allowed: derived from rbias instead
    float* out = (float*)d_out;

    proj_kernel<<<256, 256>>>(x, Wq, Wk, Wv);
    attn_kernel<<<dim3(64, 8), 128>>>(rbias, out);
}

// round 6
// speedup vs baseline: 2.2471x; 1.1877x over previous
#include <cuda_runtime.h>

#define TT 2048
#define BB 8
#define CC 1024
#define HH 64

typedef unsigned long long u64;

// ---- packed fp32x2 helpers (sm_100+ PTX; exact IEEE fp32 semantics) ----
__device__ __forceinline__ u64 pk2(float lo, float hi) {
    u64 r; asm("mov.b64 %0, {%1,%2};" : "=l"(r) : "f"(lo), "f"(hi)); return r;
}
__device__ __forceinline__ u64 pkd(float v) { return pk2(v, v); }
__device__ __forceinline__ void upk(u64 v, float& lo, float& hi) {
    asm("mov.b64 {%0,%1}, %2;" : "=f"(lo), "=f"(hi) : "l"(v));
}
__device__ __forceinline__ u64 fma2(u64 a, u64 b, u64 c) {
    u64 d; asm("fma.rn.f32x2 %0, %1, %2, %3;" : "=l"(d) : "l"(a), "l"(b), "l"(c)); return d;
}
__device__ __forceinline__ u64 mul2(u64 a, u64 b) {
    u64 d; asm("mul.rn.f32x2 %0, %1, %2;" : "=l"(d) : "l"(a), "l"(b)); return d;
}

// Scratch: projected q/k/v [B,T,H] fp32 (4 MB each) + split-K partials.
__device__ float g_q[BB * TT * HH];
__device__ float g_k[BB * TT * HH];
__device__ float g_v[BB * TT * HH];
__device__ float g_po[2 * BB * TT * HH];   // unnormalized partial O per half
__device__ float g_pm[2 * BB * TT];        // running max per half
__device__ float g_pl[2 * BB * TT];        // running denom per half

// ---------------------------------------------------------------------------
// Kernel 1: fused QKV projection.  [16384 x 1024] @ [1024 x 192]
// 64x192 tile, k-chunk 16, register-prefetch double buffering, FFMA2.
// ---------------------------------------------------------------------------
__global__ __launch_bounds__(256) void proj_kernel(
    const float* __restrict__ x,
    const float* __restrict__ Wq,
    const float* __restrict__ Wk,
    const float* __restrict__ Wv)
{
    __shared__ __align__(16) float xs[16][68];    // [kk][row]  (transposed)
    __shared__ __align__(16) float ws[16][196];   // [kk][col 0..191]

    const int tid = threadIdx.x;
    const int g = tid >> 4;
    const int tx = tid & 15;
    const int R = g * 4;
    const int c0 = tx * 12;
    const int row0 = blockIdx.x * 64;

    u64 acc[4][6];
#pragma unroll
    for (int i = 0; i < 4; i++)
#pragma unroll
        for (int j = 0; j < 6; j++) acc[i][j] = 0ull;

    const int xr = tid >> 2;
    const int xseg = (tid & 3) * 4;
    const float* xp = x + (size_t)(row0 + xr) * CC + xseg;

    int wkk[3], wh[3];
    const float* wp[3];
#pragma unroll
    for (int i = 0; i < 3; i++) {
        int idx4 = tid + 256 * i;
        wkk[i] = idx4 / 48;
        wh[i] = 4 * (idx4 - 48 * wkk[i]);
        int h = wh[i];
        wp[i] = (h < 64) ? (Wq + h) : (h < 128) ? (Wk + (h - 64)) : (Wv + (h - 128));
    }

    float4 xv = *(const float4*)(xp);
    float4 wv[3];
#pragma unroll
    for (int i = 0; i < 3; i++)
        wv[i] = *(const float4*)(wp[i] + (size_t)wkk[i] * 64);

    for (int k0 = 0; k0 < CC; k0 += 16) {
        xs[xseg + 0][xr] = xv.x;
        xs[xseg + 1][xr] = xv.y;
        xs[xseg + 2][xr] = xv.z;
        xs[xseg + 3][xr] = xv.w;
#pragma unroll
        for (int i = 0; i < 3; i++)
            *(float4*)&ws[wkk[i]][wh[i]] = wv[i];
        __syncthreads();

        if (k0 + 16 < CC) {
            xv = *(const float4*)(xp + k0 + 16);
#pragma unroll
            for (int i = 0; i < 3; i++)
                wv[i] = *(const float4*)(wp[i] + (size_t)(k0 + 16 + wkk[i]) * 64);
        }

#pragma unroll
        for (int kk = 0; kk < 16; kk++) {
            float4 a = *(const float4*)&xs[kk][R];
            u64 a0 = pkd(a.x), a1 = pkd(a.y), a2 = pkd(a.z), a3 = pkd(a.w);
            const ulonglong2* bp = (const ulonglong2*)&ws[kk][c0];
            ulonglong2 b01 = bp[0], b23 = bp[1], b45 = bp[2];
            u64 b[6] = {b01.x, b01.y, b23.x, b23.y, b45.x, b45.y};
#pragma unroll
            for (int j = 0; j < 6; j++) {
                acc[0][j] = fma2(a0, b[j], acc[0][j]);
                acc[1][j] = fma2(a1, b[j], acc[1][j]);
                acc[2][j] = fma2(a2, b[j], acc[2][j]);
                acc[3][j] = fma2(a3, b[j], acc[3][j]);
            }
        }
        __syncthreads();
    }

#pragma unroll
    for (int i = 0; i < 4; i++) {
        size_t r = (size_t)(row0 + R + i);
#pragma unroll
        for (int j = 0; j < 6; j++) {
            float lo, hi; upk(acc[i][j], lo, hi);
            int cc = c0 + 2 * j;
            int seg = cc >> 6, off = cc & 63;
            float* base = (seg == 0) ? g_q : (seg == 1) ? g_k : g_v;
            float2 val; val.x = lo; val.y = hi;
            *(float2*)&base[r * 64 + off] = val;
        }
    }
}

// ---------------------------------------------------------------------------
// Kernel 2: split-K flash attention with resonance bias/mask.
// Block = (qtile, batch, half). 32-query tile, 128 threads, 32-key tiles.
// Softmax state (m, l) lives in registers; row reductions via 16-lane
// xor-butterflies (rows are lane-uniform within each 16-thread group).
// Each half writes unnormalized partial O + (m, l); combine merges.
// ---------------------------------------------------------------------------
__global__ __launch_bounds__(128) void attn_kernel(
    const float* __restrict__ rbias)
{
    __shared__ __align__(16) float qs[64][36];   // [h][row]
    __shared__ __align__(16) float ks[64][34];   // [h][key]
    __shared__ __align__(16) float vs[32][68];   // [key][h]
    __shared__ __align__(16) float ss[32][36];   // [row][key] (p values)

    const int b = blockIdx.y;
    const int half = blockIdx.z;
    const int qb = 63 - blockIdx.x;      // heavy tiles first
    const int q0 = qb * 32;
    const int tid = threadIdx.x;
    const int g = tid >> 4;              // 0..7
    const int tx = tid & 15;             // 0..15
    const int R = g * 4;                 // row base
    const int c2 = tx * 2;               // S col pair base
    const int c4 = tx * 4;               // PV/O col base

    // Load Q tile (32 x 64) transposed into qs[h][r]
#pragma unroll
    for (int i = 0; i < 4; i++) {
        int idx = tid + 128 * i;
        int r = idx >> 4;
        int hs = (idx & 15) * 4;
        float4 v = *(const float4*)&g_q[((size_t)(b * TT + q0 + r)) * HH + hs];
        qs[hs + 0][r] = v.x; qs[hs + 1][r] = v.y;
        qs[hs + 2][r] = v.z; qs[hs + 3][r] = v.w;
    }

    float m[4], l[4];
    u64 o[4][2];
#pragma unroll
    for (int i = 0; i < 4; i++) {
        m[i] = -1e30f; l[i] = 0.f; o[i][0] = 0ull; o[i][1] = 0ull;
    }

    const int nkb = qb + 1;              // key tiles cover [0, q0+32)
    const int kb_beg = half ? (nkb + 1) / 2 : 0;
    const int kb_end = half ? nkb : (nkb + 1) / 2;

    for (int kb = kb_beg; kb < kb_end; kb++) {
        const int k0 = kb * 32;
        __syncthreads();   // protect ks/vs/ss (and initial qs stores)

        // Load K (transposed) and V (row-major) tiles
#pragma unroll
        for (int i = 0; i < 4; i++) {
            int idx = tid + 128 * i;
            int r = idx >> 4;
            int hs = (idx & 15) * 4;
            size_t gi = ((size_t)(b * TT + k0 + r)) * HH + hs;
            float4 kv = *(const float4*)&g_k[gi];
            ks[hs + 0][r] = kv.x; ks[hs + 1][r] = kv.y;
            ks[hs + 2][r] = kv.z; ks[hs + 3][r] = kv.w;
            float4 vv = *(const float4*)&g_v[gi];
            *(float4*)&vs[r][hs] = vv;
        }
        __syncthreads();

        // S = Q K^T : 4 rows x 2 packed cols per thread
        u64 acc[4] = {0ull, 0ull, 0ull, 0ull};
#pragma unroll
        for (int h = 0; h < 64; h++) {
            float4 a = *(const float4*)&qs[h][R];
            u64 kk2 = *(const u64*)&ks[h][c2];
            acc[0] = fma2(pkd(a.x), kk2, acc[0]);
            acc[1] = fma2(pkd(a.y), kk2, acc[1]);
            acc[2] = fma2(pkd(a.z), kk2, acc[2]);
            acc[3] = fma2(pkd(a.w), kk2, acc[3]);
        }

        // scale + bias + mask, row-max butterflies, exp, row-sum butterflies
        float s0[4], s1[4], mx[4];
#pragma unroll
        for (int i = 0; i < 4; i++) {
            int qi = q0 + R + i;
            int kj = k0 + c2;
            float2 bb = *(const float2*)&rbias[(size_t)qi * TT + kj];
            float lo, hi; upk(acc[i], lo, hi);
            bool al0 = (kj <= qi) && (bb.x > 0.f || kj == qi);
            bool al1 = (kj + 1 <= qi) && (bb.y > 0.f || kj + 1 == qi);
            s0[i] = al0 ? fmaf(lo, 0.03125f, bb.x) : -1e30f;
            s1[i] = al1 ? fmaf(hi, 0.03125f, bb.y) : -1e30f;
            mx[i] = fmaxf(s0[i], s1[i]);
        }
#pragma unroll
        for (int st = 1; st <= 8; st <<= 1)
#pragma unroll
            for (int i = 0; i < 4; i++)
                mx[i] = fmaxf(mx[i], __shfl_xor_sync(0xffffffffu, mx[i], st));

        float sum[4];
#pragma unroll
        for (int i = 0; i < 4; i++) {
            float m_new = fmaxf(m[i], mx[i]);
            float base = fmaxf(m_new, -1e28f);
            float p0 = __expf(s0[i] - base);
            float p1 = __expf(s1[i] - base);
            sum[i] = p0 + p1;
            float cr = __expf(m[i] - m_new);
            l[i] *= cr;
            m[i] = m_new;
            u64 crd = pkd(cr);
            o[i][0] = mul2(o[i][0], crd);
            o[i][1] = mul2(o[i][1], crd);
            *(u64*)&ss[R + i][c2] = pk2(p0, p1);
        }
#pragma unroll
        for (int st = 1; st <= 8; st <<= 1)
#pragma unroll
            for (int i = 0; i < 4; i++)
                sum[i] += __shfl_xor_sync(0xffffffffu, sum[i], st);
#pragma unroll
        for (int i = 0; i < 4; i++) l[i] += sum[i];
        __syncthreads();

        // O += P @ V : 4 rows x 4 packed cols, float4 p loads (broadcast)
#pragma unroll
        for (int cg = 0; cg < 32; cg += 4) {
            float4 pr[4];
#pragma unroll
            for (int i = 0; i < 4; i++) pr[i] = *(const float4*)&ss[R + i][cg];
#pragma unroll
            for (int cc = 0; cc < 4; cc++) {
                ulonglong2 v2 = *(const ulonglong2*)&vs[cg + cc][c4];
#pragma unroll
                for (int i = 0; i < 4; i++) {
                    float pv = (cc == 0) ? pr[i].x : (cc == 1) ? pr[i].y
                             : (cc == 2) ? pr[i].z : pr[i].w;
                    u64 p = pkd(pv);
                    o[i][0] = fma2(p, v2.x, o[i][0]);
                    o[i][1] = fma2(p, v2.y, o[i][1]);
                }
            }
        }
    }

    // epilogue: write partial (unnormalized O, m, l)
    const size_t hoff = (size_t)half * (BB * TT * HH);
#pragma unroll
    for (int i = 0; i < 4; i++) {
        int row = b * TT + q0 + R + i;
        float a0, a1, a2, a3;
        upk(o[i][0], a0, a1);
        upk(o[i][1], a2, a3);
        float4 ov; ov.x = a0; ov.y = a1; ov.z = a2; ov.w = a3;
        *(float4*)&g_po[hoff + (size_t)row * HH + c4] = ov;
        if (tx == 0) {
            g_pm[half * (BB * TT) + row] = m[i];
            g_pl[half * (BB * TT) + row] = l[i];
        }
    }
}

// ---------------------------------------------------------------------------
// Kernel 3: merge the two split-K halves and normalize.
// ---------------------------------------------------------------------------
__global__ __launch_bounds__(256) void combine_kernel(float* __restrict__ out)
{
    int idx = blockIdx.x * 256 + threadIdx.x;   // 0 .. 262143
    int e = idx * 4;
    int row = e >> 6;
    float m0 = g_pm[row], m1 = g_pm[BB * TT + row];
    float l0 = g_pl[row], l1 = g_pl[BB * TT + row];
    float mm = fmaxf(m0, m1);
    float a0 = __expf(m0 - mm);
    float a1 = __expf(m1 - mm);
    float inv = 1.f / (l0 * a0 + l1 * a1);
    float4 x0 = *(const float4*)&g_po[e];
    float4 x1 = *(const float4*)&g_po[BB * TT * HH + e];
    float4 r;
    r.x = (x0.x * a0 + x1.x * a1) * inv;
    r.y = (x0.y * a0 + x1.y * a1) * inv;
    r.z = (x0.z * a0 + x1.z * a1) * inv;
    r.w = (x0.w * a0 + x1.w * a1) * inv;
    *(float4*)&out[e] = r;
}

// ---------------------------------------------------------------------------
// Inputs (metadata order): x, Wq, Wk, Wv, rbias, allowed
// Output: [B, T, H] float32
// ---------------------------------------------------------------------------
extern "C" void kernel_launch(void* const* d_in, const int* in_sizes, int n_in,
                              void* d_out, int out_size)
{
    const float* x     = (const float*)d_in[0];
    const float* Wq    = (const float*)d_in[1];
    const float* Wk    = (const float*)d_in[2];
    const float* Wv    = (const float*)d_in[3];
    const float* rbias = (const float*)d_in[4];
    // d_in[5] = allowed: derived from rbias instead
    float* out = (float*)d_out;

    proj_kernel<<<256, 256>>>(x, Wq, Wk, Wv);
    attn_kernel<<<dim3(64, 8, 2), 128>>>(rbias);
    combine_kernel<<<1024, 256>>>(out);
}

// round 9
// speedup vs baseline: 3.0208x; 1.3443x over previous
#include <cuda_runtime.h>
#include <cstdint>

#define TT 2048
#define BB 8
#define CC 1024
#define HH 64

typedef unsigned long long u64;

// ---- packed fp32x2 helpers (exact IEEE fp32 semantics) ----
__device__ __forceinline__ u64 pk2(float lo, float hi) {
    u64 r; asm("mov.b64 %0, {%1,%2};" : "=l"(r) : "f"(lo), "f"(hi)); return r;
}
__device__ __forceinline__ u64 pkd(float v) { return pk2(v, v); }
__device__ __forceinline__ void upk(u64 v, float& lo, float& hi) {
    asm("mov.b64 {%0,%1}, %2;" : "=f"(lo), "=f"(hi) : "l"(v));
}
__device__ __forceinline__ u64 fma2(u64 a, u64 b, u64 c) {
    u64 d; asm("fma.rn.f32x2 %0, %1, %2, %3;" : "=l"(d) : "l"(a), "l"(b), "l"(c)); return d;
}
__device__ __forceinline__ u64 mul2(u64 a, u64 b) {
    u64 d; asm("mul.rn.f32x2 %0, %1, %2;" : "=l"(d) : "l"(a), "l"(b)); return d;
}

__device__ __forceinline__ uint32_t cvt_tf32(float v) {
    uint32_t t; asm("cvt.rna.tf32.f32 %0, %1;" : "=r"(t) : "f"(v)); return t;
}
__device__ __forceinline__ uint32_t smem_u32(const void* p) {
    uint32_t a;
    asm("{ .reg .u64 t; cvta.to.shared.u64 t, %1; cvt.u32.u64 %0, t; }" : "=r"(a) : "l"(p));
    return a;
}
// HMMA tf32: D(16x8) += A(16x8) * B(8x8); base ISA (sm_80+), no 'a' target needed.
__device__ __forceinline__ void mma_tf32(float* c, const uint32_t* a,
                                         uint32_t b0, uint32_t b1) {
    asm volatile(
        "mma.sync.aligned.m16n8k8.row.col.f32.tf32.tf32.f32 "
        "{%0,%1,%2,%3}, {%4,%5,%6,%7}, {%8,%9}, {%0,%1,%2,%3};"
        : "+f"(c[0]), "+f"(c[1]), "+f"(c[2]), "+f"(c[3])
        : "r"(a[0]), "r"(a[1]), "r"(a[2]), "r"(a[3]), "r"(b0), "r"(b1));
}
__device__ __forceinline__ void ldsm_x4(uint32_t* r, uint32_t addr) {
    asm volatile("ldmatrix.sync.aligned.m8n8.x4.shared.b16 {%0,%1,%2,%3}, [%4];"
                 : "=r"(r[0]), "=r"(r[1]), "=r"(r[2]), "=r"(r[3]) : "r"(addr));
}

// Scratch: projected q/k/v [B,T,H] fp32 + split-K partials.
__device__ float g_q[BB * TT * HH];
__device__ float g_k[BB * TT * HH];
__device__ float g_v[BB * TT * HH];
__device__ float g_po[2 * BB * TT * HH];
__device__ float g_pm[2 * BB * TT];
__device__ float g_pl[2 * BB * TT];

// ---------------------------------------------------------------------------
// Kernel 1: tf32 HMMA QKV projection.  [16384 x 1024] @ [1024 x 192]
// CTA = 128 rows x 192 cols, 8 warps (warp tile 32 x 96 = 2 m16 x 12 n8),
// K chunks of 32 in smem, register-prefetch double buffering.
// A pad 36 (conflict-free 4g+t), B pad 200 (conflict-free 8t+g).
// ---------------------------------------------------------------------------
__global__ __launch_bounds__(256) void proj_kernel(
    const float* __restrict__ x,
    const float* __restrict__ Wq,
    const float* __restrict__ Wk,
    const float* __restrict__ Wv)
{
    __shared__ uint32_t As[128][36];   // [m][k], tf32 bits
    __shared__ uint32_t Bs[32][200];   // [k][n], tf32 bits

    const int tid = threadIdx.x;
    const int wid = tid >> 5;
    const int lane = tid & 31;
    const int g = lane >> 2;          // 0..7
    const int t = lane & 3;           // 0..3
    const int wr = wid & 3;           // warp row: 4 x 32 rows
    const int wc = wid >> 2;          // warp col: 2 x 96 cols
    const int row0 = blockIdx.x * 128;

    float c[2][12][4];
#pragma unroll
    for (int mi = 0; mi < 2; mi++)
#pragma unroll
        for (int j = 0; j < 12; j++)
#pragma unroll
            for (int q = 0; q < 4; q++) c[mi][j][q] = 0.f;

    // A fill mapping: 4 float4 per thread over 128x32
    const int ar = tid >> 3;                // 0..31 base rows (x4 via +32*i)
    const int ac = (tid & 7) * 4;           // col 0..28
    // B fill mapping: 6 float4 per thread over 32x192
    int br[6], bc[6];
    const float* wsrc[6];
#pragma unroll
    for (int i = 0; i < 6; i++) {
        int idx = tid + 256 * i;            // < 1536
        br[i] = idx / 48;                   // k row 0..31
        bc[i] = (idx - br[i] * 48) * 4;     // col 0..188
        int sgm = bc[i] >> 6;
        const float* W = (sgm == 0) ? Wq : (sgm == 1) ? Wk : Wv;
        wsrc[i] = W + (bc[i] & 63);
    }

    // prefetch chunk 0
    float4 pa[4], pb[6];
#pragma unroll
    for (int i = 0; i < 4; i++)
        pa[i] = *(const float4*)&x[(size_t)(row0 + ar + 32 * i) * CC + ac];
#pragma unroll
    for (int i = 0; i < 6; i++)
        pb[i] = *(const float4*)(wsrc[i] + (size_t)br[i] * 64);

    const uint32_t As_b = smem_u32(&As[0][0]);
    // ldmatrix row address component: row = wr*32 + mi*16 + (lane&15), col = s*8 + (lane>>4)*4
    const uint32_t lrow = wr * 32 + (lane & 15);
    const uint32_t lcol = (lane >> 4) * 4;

    for (int kc = 0; kc < 32; kc++) {
        if (kc) __syncthreads();   // previous compute done before overwrite

        // store prefetched chunk (cvt to tf32)
#pragma unroll
        for (int i = 0; i < 4; i++) {
            uint32_t* d = &As[ar + 32 * i][ac];
            d[0] = cvt_tf32(pa[i].x); d[1] = cvt_tf32(pa[i].y);
            d[2] = cvt_tf32(pa[i].z); d[3] = cvt_tf32(pa[i].w);
        }
#pragma unroll
        for (int i = 0; i < 6; i++) {
            uint32_t* d = &Bs[br[i]][bc[i]];
            d[0] = cvt_tf32(pb[i].x); d[1] = cvt_tf32(pb[i].y);
            d[2] = cvt_tf32(pb[i].z); d[3] = cvt_tf32(pb[i].w);
        }
        __syncthreads();

        // prefetch next chunk
        if (kc + 1 < 32) {
            const int k1 = (kc + 1) * 32;
#pragma unroll
            for (int i = 0; i < 4; i++)
                pa[i] = *(const float4*)&x[(size_t)(row0 + ar + 32 * i) * CC + k1 + ac];
#pragma unroll
            for (int i = 0; i < 6; i++)
                pb[i] = *(const float4*)(wsrc[i] + (size_t)(k1 + br[i]) * 64);
        }

        // compute: 4 k8 steps
#pragma unroll
        for (int s = 0; s < 4; s++) {
            uint32_t afr[2][4];
#pragma unroll
            for (int mi = 0; mi < 2; mi++)
                ldsm_x4(afr[mi],
                        As_b + ((lrow + mi * 16) * 36 + s * 8 + lcol) * 4);
#pragma unroll
            for (int j = 0; j < 12; j++) {
                int col = wc * 96 + j * 8 + g;
                uint32_t b0 = Bs[s * 8 + t][col];
                uint32_t b1 = Bs[s * 8 + t + 4][col];
                mma_tf32(c[0][j], afr[0], b0, b1);
                mma_tf32(c[1][j], afr[1], b0, b1);
            }
        }
    }

    // epilogue: C -> g_q / g_k / g_v
#pragma unroll
    for (int mi = 0; mi < 2; mi++) {
        int rb = row0 + wr * 32 + mi * 16;
#pragma unroll
        for (int j = 0; j < 12; j++) {
            int cb = wc * 96 + j * 8;
            int seg = cb >> 6;
            int off = (cb & 63) + 2 * t;
            float* base = (seg == 0) ? g_q : (seg == 1) ? g_k : g_v;
            float2 v0; v0.x = c[mi][j][0]; v0.y = c[mi][j][1];
            float2 v1; v1.x = c[mi][j][2]; v1.y = c[mi][j][3];
            *(float2*)&base[(size_t)(rb + g) * 64 + off] = v0;
            *(float2*)&base[(size_t)(rb + g + 8) * 64 + off] = v1;
        }
    }
}

// ---------------------------------------------------------------------------
// Kernel 2: split-K flash attention (unchanged, passing since round 6).
// ---------------------------------------------------------------------------
__global__ __launch_bounds__(128) void attn_kernel(
    const float* __restrict__ rbias)
{
    __shared__ __align__(16) float qs[64][36];
    __shared__ __align__(16) float ks[64][34];
    __shared__ __align__(16) float vs[32][68];
    __shared__ __align__(16) float ss[32][36];

    const int b = blockIdx.y;
    const int half = blockIdx.z;
    const int qb = 63 - blockIdx.x;
    const int q0 = qb * 32;
    const int tid = threadIdx.x;
    const int g = tid >> 4;
    const int tx = tid & 15;
    const int R = g * 4;
    const int c2 = tx * 2;
    const int c4 = tx * 4;

#pragma unroll
    for (int i = 0; i < 4; i++) {
        int idx = tid + 128 * i;
        int r = idx >> 4;
        int hs = (idx & 15) * 4;
        float4 v = *(const float4*)&g_q[((size_t)(b * TT + q0 + r)) * HH + hs];
        qs[hs + 0][r] = v.x; qs[hs + 1][r] = v.y;
        qs[hs + 2][r] = v.z; qs[hs + 3][r] = v.w;
    }

    float m[4], l[4];
    u64 o[4][2];
#pragma unroll
    for (int i = 0; i < 4; i++) {
        m[i] = -1e30f; l[i] = 0.f; o[i][0] = 0ull; o[i][1] = 0ull;
    }

    const int nkb = qb + 1;
    const int kb_beg = half ? (nkb + 1) / 2 : 0;
    const int kb_end = half ? nkb : (nkb + 1) / 2;

    for (int kb = kb_beg; kb < kb_end; kb++) {
        const int k0 = kb * 32;
        __syncthreads();

#pragma unroll
        for (int i = 0; i < 4; i++) {
            int idx = tid + 128 * i;
            int r = idx >> 4;
            int hs = (idx & 15) * 4;
            size_t gi = ((size_t)(b * TT + k0 + r)) * HH + hs;
            float4 kv = *(const float4*)&g_k[gi];
            ks[hs + 0][r] = kv.x; ks[hs + 1][r] = kv.y;
            ks[hs + 2][r] = kv.z; ks[hs + 3][r] = kv.w;
            float4 vv = *(const float4*)&g_v[gi];
            *(float4*)&vs[r][hs] = vv;
        }
        __syncthreads();

        u64 acc[4] = {0ull, 0ull, 0ull, 0ull};
#pragma unroll
        for (int h = 0; h < 64; h++) {
            float4 a = *(const float4*)&qs[h][R];
            u64 kk2 = *(const u64*)&ks[h][c2];
            acc[0] = fma2(pkd(a.x), kk2, acc[0]);
            acc[1] = fma2(pkd(a.y), kk2, acc[1]);
            acc[2] = fma2(pkd(a.z), kk2, acc[2]);
            acc[3] = fma2(pkd(a.w), kk2, acc[3]);
        }

        float s0[4], s1[4], mx[4];
#pragma unroll
        for (int i = 0; i < 4; i++) {
            int qi = q0 + R + i;
            int kj = k0 + c2;
            float2 bb = *(const float2*)&rbias[(size_t)qi * TT + kj];
            float lo, hi; upk(acc[i], lo, hi);
            bool al0 = (kj <= qi) && (bb.x > 0.f || kj == qi);
            bool al1 = (kj + 1 <= qi) && (bb.y > 0.f || kj + 1 == qi);
            s0[i] = al0 ? fmaf(lo, 0.03125f, bb.x) : -1e30f;
            s1[i] = al1 ? fmaf(hi, 0.03125f, bb.y) : -1e30f;
            mx[i] = fmaxf(s0[i], s1[i]);
        }
#pragma unroll
        for (int st = 1; st <= 8; st <<= 1)
#pragma unroll
            for (int i = 0; i < 4; i++)
                mx[i] = fmaxf(mx[i], __shfl_xor_sync(0xffffffffu, mx[i], st));

        float sum[4];
#pragma unroll
        for (int i = 0; i < 4; i++) {
            float m_new = fmaxf(m[i], mx[i]);
            float base = fmaxf(m_new, -1e28f);
            float p0 = __expf(s0[i] - base);
            float p1 = __expf(s1[i] - base);
            sum[i] = p0 + p1;
            float cr = __expf(m[i] - m_new);
            l[i] *= cr;
            m[i] = m_new;
            u64 crd = pkd(cr);
            o[i][0] = mul2(o[i][0], crd);
            o[i][1] = mul2(o[i][1], crd);
            *(u64*)&ss[R + i][c2] = pk2(p0, p1);
        }
#pragma unroll
        for (int st = 1; st <= 8; st <<= 1)
#pragma unroll
            for (int i = 0; i < 4; i++)
                sum[i] += __shfl_xor_sync(0xffffffffu, sum[i], st);
#pragma unroll
        for (int i = 0; i < 4; i++) l[i] += sum[i];
        __syncthreads();

#pragma unroll
        for (int cg = 0; cg < 32; cg += 4) {
            float4 pr[4];
#pragma unroll
            for (int i = 0; i < 4; i++) pr[i] = *(const float4*)&ss[R + i][cg];
#pragma unroll
            for (int cc = 0; cc < 4; cc++) {
                ulonglong2 v2 = *(const ulonglong2*)&vs[cg + cc][c4];
#pragma unroll
                for (int i = 0; i < 4; i++) {
                    float pv = (cc == 0) ? pr[i].x : (cc == 1) ? pr[i].y
                             : (cc == 2) ? pr[i].z : pr[i].w;
                    u64 p = pkd(pv);
                    o[i][0] = fma2(p, v2.x, o[i][0]);
                    o[i][1] = fma2(p, v2.y, o[i][1]);
                }
            }
        }
    }

    const size_t hoff = (size_t)half * (BB * TT * HH);
#pragma unroll
    for (int i = 0; i < 4; i++) {
        int row = b * TT + q0 + R + i;
        float a0, a1, a2, a3;
        upk(o[i][0], a0, a1);
        upk(o[i][1], a2, a3);
        float4 ov; ov.x = a0; ov.y = a1; ov.z = a2; ov.w = a3;
        *(float4*)&g_po[hoff + (size_t)row * HH + c4] = ov;
        if (tx == 0) {
            g_pm[half * (BB * TT) + row] = m[i];
            g_pl[half * (BB * TT) + row] = l[i];
        }
    }
}

// ---------------------------------------------------------------------------
// Kernel 3: merge split-K halves and normalize.
// ---------------------------------------------------------------------------
__global__ __launch_bounds__(256) void combine_kernel(float* __restrict__ out)
{
    int idx = blockIdx.x * 256 + threadIdx.x;
    int e = idx * 4;
    int row = e >> 6;
    float m0 = g_pm[row], m1 = g_pm[BB * TT + row];
    float l0 = g_pl[row], l1 = g_pl[BB * TT + row];
    float mm = fmaxf(m0, m1);
    float a0 = __expf(m0 - mm);
    float a1 = __expf(m1 - mm);
    float inv = 1.f / (l0 * a0 + l1 * a1);
    float4 x0 = *(const float4*)&g_po[e];
    float4 x1 = *(const float4*)&g_po[BB * TT * HH + e];
    float4 r;
    r.x = (x0.x * a0 + x1.x * a1) * inv;
    r.y = (x0.y * a0 + x1.y * a1) * inv;
    r.z = (x0.z * a0 + x1.z * a1) * inv;
    r.w = (x0.w * a0 + x1.w * a1) * inv;
    *(float4*)&out[e] = r;
}

// ---------------------------------------------------------------------------
// Inputs (metadata order): x, Wq, Wk, Wv, rbias, allowed
// Output: [B, T, H] float32
// ---------------------------------------------------------------------------
extern "C" void kernel_launch(void* const* d_in, const int* in_sizes, int n_in,
                              void* d_out, int out_size)
{
    const float* x     = (const float*)d_in[0];
    const float* Wq    = (const float*)d_in[1];
    const float* Wk    = (const float*)d_in[2];
    const float* Wv    = (const float*)d_in[3];
    const float* rbias = (const float*)d_in[4];
    float* out = (float*)d_out;

    proj_kernel<<<128, 256>>>(x, Wq, Wk, Wv);
    attn_kernel<<<dim3(64, 8, 2), 128>>>(rbias);
    combine_kernel<<<1024, 256>>>(out);
}

// round 11
// speedup vs baseline: 3.8145x; 1.2627x over previous
#include <cuda_runtime.h>
#include <cstdint>

#define TT 2048
#define BB 8
#define CC 1024
#define HH 64

typedef unsigned long long u64;

// ---- packed fp32x2 helpers (exact IEEE fp32 semantics) ----
__device__ __forceinline__ u64 pk2(float lo, float hi) {
    u64 r; asm("mov.b64 %0, {%1,%2};" : "=l"(r) : "f"(lo), "f"(hi)); return r;
}
__device__ __forceinline__ u64 pkd(float v) { return pk2(v, v); }
__device__ __forceinline__ void upk(u64 v, float& lo, float& hi) {
    asm("mov.b64 {%0,%1}, %2;" : "=f"(lo), "=f"(hi) : "l"(v));
}
__device__ __forceinline__ u64 fma2(u64 a, u64 b, u64 c) {
    u64 d; asm("fma.rn.f32x2 %0, %1, %2, %3;" : "=l"(d) : "l"(a), "l"(b), "l"(c)); return d;
}
__device__ __forceinline__ u64 mul2(u64 a, u64 b) {
    u64 d; asm("mul.rn.f32x2 %0, %1, %2;" : "=l"(d) : "l"(a), "l"(b)); return d;
}

__device__ __forceinline__ uint32_t cvt_tf32(float v) {
    uint32_t t; asm("cvt.rna.tf32.f32 %0, %1;" : "=r"(t) : "f"(v)); return t;
}
__device__ __forceinline__ uint32_t smem_u32(const void* p) {
    uint32_t a;
    asm("{ .reg .u64 t; cvta.to.shared.u64 t, %1; cvt.u32.u64 %0, t; }" : "=r"(a) : "l"(p));
    return a;
}
// HMMA tf32: D(16x8) += A(16x8) * B(8x8); base ISA (sm_80+).
__device__ __forceinline__ void mma_tf32(float* c, const uint32_t* a,
                                         uint32_t b0, uint32_t b1) {
    asm volatile(
        "mma.sync.aligned.m16n8k8.row.col.f32.tf32.tf32.f32 "
        "{%0,%1,%2,%3}, {%4,%5,%6,%7}, {%8,%9}, {%0,%1,%2,%3};"
        : "+f"(c[0]), "+f"(c[1]), "+f"(c[2]), "+f"(c[3])
        : "r"(a[0]), "r"(a[1]), "r"(a[2]), "r"(a[3]), "r"(b0), "r"(b1));
}
__device__ __forceinline__ void ldsm_x4(uint32_t* r, uint32_t addr) {
    asm volatile("ldmatrix.sync.aligned.m8n8.x4.shared.b16 {%0,%1,%2,%3}, [%4];"
                 : "=r"(r[0]), "=r"(r[1]), "=r"(r[2]), "=r"(r[3]) : "r"(addr));
}

// Scratch: projected q/k/v [B,T,H] fp32 + split-K partials.
__device__ float g_q[BB * TT * HH];
__device__ float g_k[BB * TT * HH];
__device__ float g_v[BB * TT * HH];
__device__ float g_po[2 * BB * TT * HH];
__device__ float g_pm[2 * BB * TT];
__device__ float g_pl[2 * BB * TT];

// ---------------------------------------------------------------------------
// Kernel 1: tf32 HMMA QKV projection.  [16384 x 1024] @ [1024 x 192]
// CTA = 64 rows x 192 cols (grid 256 -> all SMs busy), 8 warps:
// warp tile 32 x 48 (2 m16 x 6 n8), K chunks of 32, register prefetch.
// ---------------------------------------------------------------------------
__global__ __launch_bounds__(256) void proj_kernel(
    const float* __restrict__ x,
    const float* __restrict__ Wq,
    const float* __restrict__ Wk,
    const float* __restrict__ Wv)
{
    __shared__ uint32_t As[64][36];    // [m][k], tf32 bits
    __shared__ uint32_t Bs[32][200];   // [k][n], tf32 bits

    const int tid = threadIdx.x;
    const int wid = tid >> 5;
    const int lane = tid & 31;
    const int g = lane >> 2;
    const int t = lane & 3;
    const int wr = wid & 1;           // 2 x 32 rows
    const int wc = wid >> 1;          // 4 x 48 cols
    const int row0 = blockIdx.x * 64;

    float c[2][6][4];
#pragma unroll
    for (int mi = 0; mi < 2; mi++)
#pragma unroll
        for (int j = 0; j < 6; j++)
#pragma unroll
            for (int q = 0; q < 4; q++) c[mi][j][q] = 0.f;

    // A fill: 2 float4 per thread over 64x32
    const int ar = tid >> 3;                // 0..31 (+32)
    const int ac = (tid & 7) * 4;
    // B fill: 6 float4 per thread over 32x192
    int br[6], bc[6];
    const float* wsrc[6];
#pragma unroll
    for (int i = 0; i < 6; i++) {
        int idx = tid + 256 * i;
        br[i] = idx / 48;
        bc[i] = (idx - br[i] * 48) * 4;
        int sgm = bc[i] >> 6;
        const float* W = (sgm == 0) ? Wq : (sgm == 1) ? Wk : Wv;
        wsrc[i] = W + (bc[i] & 63);
    }

    float4 pa[2], pb[6];
#pragma unroll
    for (int i = 0; i < 2; i++)
        pa[i] = *(const float4*)&x[(size_t)(row0 + ar + 32 * i) * CC + ac];
#pragma unroll
    for (int i = 0; i < 6; i++)
        pb[i] = *(const float4*)(wsrc[i] + (size_t)br[i] * 64);

    const uint32_t As_b = smem_u32(&As[0][0]);
    const uint32_t lrow = wr * 32 + (lane & 15);
    const uint32_t lcol = (lane >> 4) * 4;

    for (int kc = 0; kc < 32; kc++) {
        if (kc) __syncthreads();

#pragma unroll
        for (int i = 0; i < 2; i++) {
            uint32_t* d = &As[ar + 32 * i][ac];
            d[0] = cvt_tf32(pa[i].x); d[1] = cvt_tf32(pa[i].y);
            d[2] = cvt_tf32(pa[i].z); d[3] = cvt_tf32(pa[i].w);
        }
#pragma unroll
        for (int i = 0; i < 6; i++) {
            uint32_t* d = &Bs[br[i]][bc[i]];
            d[0] = cvt_tf32(pb[i].x); d[1] = cvt_tf32(pb[i].y);
            d[2] = cvt_tf32(pb[i].z); d[3] = cvt_tf32(pb[i].w);
        }
        __syncthreads();

        if (kc + 1 < 32) {
            const int k1 = (kc + 1) * 32;
#pragma unroll
            for (int i = 0; i < 2; i++)
                pa[i] = *(const float4*)&x[(size_t)(row0 + ar + 32 * i) * CC + k1 + ac];
#pragma unroll
            for (int i = 0; i < 6; i++)
                pb[i] = *(const float4*)(wsrc[i] + (size_t)(k1 + br[i]) * 64);
        }

#pragma unroll
        for (int s = 0; s < 4; s++) {
            uint32_t afr[2][4];
#pragma unroll
            for (int mi = 0; mi < 2; mi++)
                ldsm_x4(afr[mi], As_b + ((lrow + mi * 16) * 36 + s * 8 + lcol) * 4);
#pragma unroll
            for (int j = 0; j < 6; j++) {
                int col = wc * 48 + j * 8 + g;
                uint32_t b0 = Bs[s * 8 + t][col];
                uint32_t b1 = Bs[s * 8 + t + 4][col];
                mma_tf32(c[0][j], afr[0], b0, b1);
                mma_tf32(c[1][j], afr[1], b0, b1);
            }
        }
    }

#pragma unroll
    for (int mi = 0; mi < 2; mi++) {
        int rb = row0 + wr * 32 + mi * 16;
#pragma unroll
        for (int j = 0; j < 6; j++) {
            int cb = wc * 48 + j * 8;
            int seg = cb >> 6;
            int off = (cb & 63) + 2 * t;
            float* base = (seg == 0) ? g_q : (seg == 1) ? g_k : g_v;
            float2 v0; v0.x = c[mi][j][0]; v0.y = c[mi][j][1];
            float2 v1; v1.x = c[mi][j][2]; v1.y = c[mi][j][3];
            *(float2*)&base[(size_t)(rb + g) * 64 + off] = v0;
            *(float2*)&base[(size_t)(rb + g + 8) * 64 + off] = v1;
        }
    }
}

// ---------------------------------------------------------------------------
// Kernel 2: split-K flash attention, S = QK^T via tf32 HMMA, PV via FFMA2.
// CTA = 64-row q tile, 128 threads (4 warps, warp w owns rows w*16..+15).
// Q fragments preloaded once via ldmatrix (qs pitch 68 — full 64-h rows!).
// K tile [key][h] tf32, pitch 68 -> conflict-free B loads. Softmax in
// C-fragment layout with quad shuffles. PV fp32 FFMA2.
// ---------------------------------------------------------------------------
__global__ __launch_bounds__(128) void attn_kernel(
    const float* __restrict__ rbias)
{
    __shared__ uint32_t qs[64][68];    // tf32 bits, [row][h]  (64 h + pad 4)
    __shared__ uint32_t ks[32][68];    // tf32 bits, [key][h]
    __shared__ float    vs[32][68];    // fp32, [key][h]
    __shared__ float    ss[64][36];    // p values, [row][key-local]
    __shared__ float    corr[64], m_s[64], l_s[64];

    const int b = blockIdx.y;
    const int half = blockIdx.z;
    const int qb = 31 - blockIdx.x;      // heavy tiles first
    const int q0 = qb * 64;
    const int tid = threadIdx.x;
    const int w = tid >> 5;
    const int lane = tid & 31;
    const int gq = lane >> 2;            // 0..7
    const int t = lane & 3;              // 0..3
    // PV mapping
    const int Rv = (tid >> 4) * 8;       // 8 rows per 16-thread group
    const int tx = tid & 15;
    const int c4 = tx * 4;

    // Load Q tile (64 x 64) -> qs tf32
#pragma unroll
    for (int i = 0; i < 8; i++) {
        int idx = tid + 128 * i;
        int r = idx >> 4, hs = (idx & 15) * 4;
        float4 v = *(const float4*)&g_q[((size_t)(b * TT + q0 + r)) * HH + hs];
        uint32_t* d = &qs[r][hs];
        d[0] = cvt_tf32(v.x); d[1] = cvt_tf32(v.y);
        d[2] = cvt_tf32(v.z); d[3] = cvt_tf32(v.w);
    }
    __syncthreads();

    // Preload Q fragments for all 8 k8-steps (rows fixed per warp)
    uint32_t qfr[8][4];
    {
        const uint32_t qs_b = smem_u32(&qs[0][0]);
        const uint32_t lrow = w * 16 + (lane & 15);
        const uint32_t lcol = (lane >> 4) * 4;
#pragma unroll
        for (int s = 0; s < 8; s++)
            ldsm_x4(qfr[s], qs_b + (lrow * 68 + s * 8 + lcol) * 4);
    }

    const int rA = w * 16 + gq;          // CTA-local softmax rows
    const int rB = rA + 8;
    const int qiA = q0 + rA, qiB = q0 + rB;
    float m0 = -1e30f, m1 = -1e30f, l0 = 0.f, l1 = 0.f;

    u64 o[8][2];
#pragma unroll
    for (int i = 0; i < 8; i++) { o[i][0] = 0ull; o[i][1] = 0ull; }

    const int nkb = 2 * qb + 2;          // 32-key tiles covering [0, q0+64)
    const int kb_beg = half ? nkb / 2 : 0;
    const int kb_end = half ? nkb : nkb / 2;

    for (int kb = kb_beg; kb < kb_end; kb++) {
        const int k0 = kb * 32;
        __syncthreads();   // previous PV done before ks/vs overwrite

        // Load K (tf32) and V (fp32) tiles, [key][h]
#pragma unroll
        for (int i = 0; i < 4; i++) {
            int idx = tid + 128 * i;
            int r = idx >> 4, hs = (idx & 15) * 4;
            size_t gi = ((size_t)(b * TT + k0 + r)) * HH + hs;
            float4 kv = *(const float4*)&g_k[gi];
            uint32_t* kd = &ks[r][hs];
            kd[0] = cvt_tf32(kv.x); kd[1] = cvt_tf32(kv.y);
            kd[2] = cvt_tf32(kv.z); kd[3] = cvt_tf32(kv.w);
            *(float4*)&vs[r][hs] = *(const float4*)&g_v[gi];
        }
        __syncthreads();

        // S = Q K^T : per warp m16 x n32 (4 n8 frags), 8 k8 steps
        float c[4][4];
#pragma unroll
        for (int j = 0; j < 4; j++)
#pragma unroll
            for (int q = 0; q < 4; q++) c[j][q] = 0.f;
#pragma unroll
        for (int s = 0; s < 8; s++) {
#pragma unroll
            for (int j = 0; j < 4; j++) {
                uint32_t b0 = ks[j * 8 + gq][s * 8 + t];
                uint32_t b1 = ks[j * 8 + gq][s * 8 + t + 4];
                mma_tf32(c[j], qfr[s], b0, b1);
            }
        }

        // Epilogue in fragment layout: scale + bias + mask
        float sA[8], sB[8];
        float mxA = -1e30f, mxB = -1e30f;
#pragma unroll
        for (int j = 0; j < 4; j++) {
            int kj = k0 + j * 8 + 2 * t;
            float2 ba = *(const float2*)&rbias[(size_t)qiA * TT + kj];
            float2 bbv = *(const float2*)&rbias[(size_t)qiB * TT + kj];
            bool a0 = (kj <= qiA) && (ba.x > 0.f || kj == qiA);
            bool a1 = (kj + 1 <= qiA) && (ba.y > 0.f || kj + 1 == qiA);
            bool b0k = (kj <= qiB) && (bbv.x > 0.f || kj == qiB);
            bool b1k = (kj + 1 <= qiB) && (bbv.y > 0.f || kj + 1 == qiB);
            sA[2 * j]     = a0 ? fmaf(c[j][0], 0.03125f, ba.x) : -1e30f;
            sA[2 * j + 1] = a1 ? fmaf(c[j][1], 0.03125f, ba.y) : -1e30f;
            sB[2 * j]     = b0k ? fmaf(c[j][2], 0.03125f, bbv.x) : -1e30f;
            sB[2 * j + 1] = b1k ? fmaf(c[j][3], 0.03125f, bbv.y) : -1e30f;
            mxA = fmaxf(mxA, fmaxf(sA[2 * j], sA[2 * j + 1]));
            mxB = fmaxf(mxB, fmaxf(sB[2 * j], sB[2 * j + 1]));
        }
        mxA = fmaxf(mxA, __shfl_xor_sync(0xffffffffu, mxA, 1));
        mxA = fmaxf(mxA, __shfl_xor_sync(0xffffffffu, mxA, 2));
        mxB = fmaxf(mxB, __shfl_xor_sync(0xffffffffu, mxB, 1));
        mxB = fmaxf(mxB, __shfl_xor_sync(0xffffffffu, mxB, 2));

        float mA = fmaxf(m0, mxA), mB = fmaxf(m1, mxB);
        float baseA = fmaxf(mA, -1e28f), baseB = fmaxf(mB, -1e28f);
        float crA = __expf(m0 - mA), crB = __expf(m1 - mB);
        m0 = mA; m1 = mB;
        float sumA = 0.f, sumB = 0.f;
#pragma unroll
        for (int jj = 0; jj < 8; jj++) {
            float pA = __expf(sA[jj] - baseA);
            float pB = __expf(sB[jj] - baseB);
            sumA += pA; sumB += pB;
            sA[jj] = pA; sB[jj] = pB;
        }
#pragma unroll
        for (int j = 0; j < 4; j++) {
            float2 wa; wa.x = sA[2 * j]; wa.y = sA[2 * j + 1];
            float2 wb; wb.x = sB[2 * j]; wb.y = sB[2 * j + 1];
            *(float2*)&ss[rA][j * 8 + 2 * t] = wa;
            *(float2*)&ss[rB][j * 8 + 2 * t] = wb;
        }
        sumA += __shfl_xor_sync(0xffffffffu, sumA, 1);
        sumA += __shfl_xor_sync(0xffffffffu, sumA, 2);
        sumB += __shfl_xor_sync(0xffffffffu, sumB, 1);
        sumB += __shfl_xor_sync(0xffffffffu, sumB, 2);
        l0 = l0 * crA + sumA;
        l1 = l1 * crB + sumB;
        if (t == 0) { corr[rA] = crA; corr[rB] = crB; }
        __syncthreads();

        // PV (fp32 FFMA2): 8 rows x 4 cols per thread
#pragma unroll
        for (int i = 0; i < 8; i++) {
            u64 cd = pkd(corr[Rv + i]);
            o[i][0] = mul2(o[i][0], cd);
            o[i][1] = mul2(o[i][1], cd);
        }
#pragma unroll
        for (int cg = 0; cg < 32; cg += 4) {
            float4 pr[8];
#pragma unroll
            for (int i = 0; i < 8; i++) pr[i] = *(const float4*)&ss[Rv + i][cg];
#pragma unroll
            for (int cc = 0; cc < 4; cc++) {
                ulonglong2 v2 = *(const ulonglong2*)&vs[cg + cc][c4];
#pragma unroll
                for (int i = 0; i < 8; i++) {
                    float pv = (cc == 0) ? pr[i].x : (cc == 1) ? pr[i].y
                             : (cc == 2) ? pr[i].z : pr[i].w;
                    u64 p = pkd(pv);
                    o[i][0] = fma2(p, v2.x, o[i][0]);
                    o[i][1] = fma2(p, v2.y, o[i][1]);
                }
            }
        }
    }

    // publish softmax state, then write partials
    if (t == 0) {
        m_s[rA] = m0; l_s[rA] = l0;
        m_s[rB] = m1; l_s[rB] = l1;
    }
    __syncthreads();

    const size_t hoff = (size_t)half * (BB * TT * HH);
#pragma unroll
    for (int i = 0; i < 8; i++) {
        int row = b * TT + q0 + Rv + i;
        float a0, a1, a2, a3;
        upk(o[i][0], a0, a1);
        upk(o[i][1], a2, a3);
        float4 ov; ov.x = a0; ov.y = a1; ov.z = a2; ov.w = a3;
        *(float4*)&g_po[hoff + (size_t)row * HH + c4] = ov;
        if (tx == 0) {
            g_pm[half * (BB * TT) + row] = m_s[Rv + i];
            g_pl[half * (BB * TT) + row] = l_s[Rv + i];
        }
    }
}

// ---------------------------------------------------------------------------
// Kernel 3: merge split-K halves and normalize.
// ---------------------------------------------------------------------------
__global__ __launch_bounds__(256) void combine_kernel(float* __restrict__ out)
{
    int idx = blockIdx.x * 256 + threadIdx.x;
    int e = idx * 4;
    int row = e >> 6;
    float m0 = g_pm[row], m1 = g_pm[BB * TT + row];
    float l0 = g_pl[row], l1 = g_pl[BB * TT + row];
    float mm = fmaxf(m0, m1);
    float a0 = __expf(m0 - mm);
    float a1 = __expf(m1 - mm);
    float inv = 1.f / (l0 * a0 + l1 * a1);
    float4 x0 = *(const float4*)&g_po[e];
    float4 x1 = *(const float4*)&g_po[BB * TT * HH + e];
    float4 r;
    r.x = (x0.x * a0 + x1.x * a1) * inv;
    r.y = (x0.y * a0 + x1.y * a1) * inv;
    r.z = (x0.z * a0 + x1.z * a1) * inv;
    r.w = (x0.w * a0 + x1.w * a1) * inv;
    *(float4*)&out[e] = r;
}

// ---------------------------------------------------------------------------
// Inputs (metadata order): x, Wq, Wk, Wv, rbias, allowed
// Output: [B, T, H] float32
// ---------------------------------------------------------------------------
extern "C" void kernel_launch(void* const* d_in, const int* in_sizes, int n_in,
                              void* d_out, int out_size)
{
    const float* x     = (const float*)d_in[0];
    const float* Wq    = (const float*)d_in[1];
    const float* Wk    = (const float*)d_in[2];
    const float* Wv    = (const float*)d_in[3];
    const float* rbias = (const float*)d_in[4];
    float* out = (float*)d_out;

    proj_kernel<<<256, 256>>>(x, Wq, Wk, Wv);
    attn_kernel<<<dim3(32, 8, 2), 128>>>(rbias);
    combine_kernel<<<1024, 256>>>(out);
}

// round 12
// speedup vs baseline: 4.8875x; 1.2813x over previous
#include <cuda_runtime.h>
#include <cstdint>

#define TT 2048
#define BB 8
#define CC 1024
#define HH 64

typedef unsigned long long u64;

// ---- packed fp32x2 helpers ----
__device__ __forceinline__ u64 pk2(float lo, float hi) {
    u64 r; asm("mov.b64 %0, {%1,%2};" : "=l"(r) : "f"(lo), "f"(hi)); return r;
}
__device__ __forceinline__ u64 pkd(float v) { return pk2(v, v); }
__device__ __forceinline__ void upk(u64 v, float& lo, float& hi) {
    asm("mov.b64 {%0,%1}, %2;" : "=f"(lo), "=f"(hi) : "l"(v));
}
__device__ __forceinline__ u64 fma2(u64 a, u64 b, u64 c) {
    u64 d; asm("fma.rn.f32x2 %0, %1, %2, %3;" : "=l"(d) : "l"(a), "l"(b), "l"(c)); return d;
}
__device__ __forceinline__ u64 mul2(u64 a, u64 b) {
    u64 d; asm("mul.rn.f32x2 %0, %1, %2;" : "=l"(d) : "l"(a), "l"(b)); return d;
}

__device__ __forceinline__ uint32_t cvt_tf32(float v) {
    uint32_t t; asm("cvt.rna.tf32.f32 %0, %1;" : "=r"(t) : "f"(v)); return t;
}
__device__ __forceinline__ uint32_t smem_u32(const void* p) {
    uint32_t a;
    asm("{ .reg .u64 t; cvta.to.shared.u64 t, %1; cvt.u32.u64 %0, t; }" : "=r"(a) : "l"(p));
    return a;
}
// HMMA tf32: D(16x8) += A(16x8) * B(8x8); base ISA (sm_80+).
__device__ __forceinline__ void mma_tf32(float* c, const uint32_t* a,
                                         uint32_t b0, uint32_t b1) {
    asm volatile(
        "mma.sync.aligned.m16n8k8.row.col.f32.tf32.tf32.f32 "
        "{%0,%1,%2,%3}, {%4,%5,%6,%7}, {%8,%9}, {%0,%1,%2,%3};"
        : "+f"(c[0]), "+f"(c[1]), "+f"(c[2]), "+f"(c[3])
        : "r"(a[0]), "r"(a[1]), "r"(a[2]), "r"(a[3]), "r"(b0), "r"(b1));
}
__device__ __forceinline__ void ldsm_x4(uint32_t* r, uint32_t addr) {
    asm volatile("ldmatrix.sync.aligned.m8n8.x4.shared.b16 {%0,%1,%2,%3}, [%4];"
                 : "=r"(r[0]), "=r"(r[1]), "=r"(r[2]), "=r"(r[3]) : "r"(addr));
}

// Scratch: projected q/k/v [B,T,H] fp32 + split-K partials.
__device__ float g_q[BB * TT * HH];
__device__ float g_k[BB * TT * HH];
__device__ float g_v[BB * TT * HH];
__device__ float g_po[2 * BB * TT * HH];
__device__ float g_pm[2 * BB * TT];
__device__ float g_pl[2 * BB * TT];

// ---------------------------------------------------------------------------
// Kernel 1: tf32 HMMA QKV projection (round-9 config: fastest measured).
// CTA = 128 rows x 192 cols, 8 warps (warp tile 32 x 96 = 2 m16 x 12 n8),
// K chunks of 32 in smem, register-prefetch double buffering.
// ---------------------------------------------------------------------------
__global__ __launch_bounds__(256) void proj_kernel(
    const float* __restrict__ x,
    const float* __restrict__ Wq,
    const float* __restrict__ Wk,
    const float* __restrict__ Wv)
{
    __shared__ uint32_t As[128][36];   // [m][k], tf32 bits
    __shared__ uint32_t Bs[32][200];   // [k][n], tf32 bits

    const int tid = threadIdx.x;
    const int wid = tid >> 5;
    const int lane = tid & 31;
    const int g = lane >> 2;
    const int t = lane & 3;
    const int wr = wid & 3;           // 4 x 32 rows
    const int wc = wid >> 2;          // 2 x 96 cols
    const int row0 = blockIdx.x * 128;

    float c[2][12][4];
#pragma unroll
    for (int mi = 0; mi < 2; mi++)
#pragma unroll
        for (int j = 0; j < 12; j++)
#pragma unroll
            for (int q = 0; q < 4; q++) c[mi][j][q] = 0.f;

    const int ar = tid >> 3;                // 0..31 base rows (x4 via +32*i)
    const int ac = (tid & 7) * 4;
    int br[6], bc[6];
    const float* wsrc[6];
#pragma unroll
    for (int i = 0; i < 6; i++) {
        int idx = tid + 256 * i;
        br[i] = idx / 48;
        bc[i] = (idx - br[i] * 48) * 4;
        int sgm = bc[i] >> 6;
        const float* W = (sgm == 0) ? Wq : (sgm == 1) ? Wk : Wv;
        wsrc[i] = W + (bc[i] & 63);
    }

    float4 pa[4], pb[6];
#pragma unroll
    for (int i = 0; i < 4; i++)
        pa[i] = *(const float4*)&x[(size_t)(row0 + ar + 32 * i) * CC + ac];
#pragma unroll
    for (int i = 0; i < 6; i++)
        pb[i] = *(const float4*)(wsrc[i] + (size_t)br[i] * 64);

    const uint32_t As_b = smem_u32(&As[0][0]);
    const uint32_t lrow = wr * 32 + (lane & 15);
    const uint32_t lcol = (lane >> 4) * 4;

    for (int kc = 0; kc < 32; kc++) {
        if (kc) __syncthreads();

#pragma unroll
        for (int i = 0; i < 4; i++) {
            uint32_t* d = &As[ar + 32 * i][ac];
            d[0] = cvt_tf32(pa[i].x); d[1] = cvt_tf32(pa[i].y);
            d[2] = cvt_tf32(pa[i].z); d[3] = cvt_tf32(pa[i].w);
        }
#pragma unroll
        for (int i = 0; i < 6; i++) {
            uint32_t* d = &Bs[br[i]][bc[i]];
            d[0] = cvt_tf32(pb[i].x); d[1] = cvt_tf32(pb[i].y);
            d[2] = cvt_tf32(pb[i].z); d[3] = cvt_tf32(pb[i].w);
        }
        __syncthreads();

        if (kc + 1 < 32) {
            const int k1 = (kc + 1) * 32;
#pragma unroll
            for (int i = 0; i < 4; i++)
                pa[i] = *(const float4*)&x[(size_t)(row0 + ar + 32 * i) * CC + k1 + ac];
#pragma unroll
            for (int i = 0; i < 6; i++)
                pb[i] = *(const float4*)(wsrc[i] + (size_t)(k1 + br[i]) * 64);
        }

#pragma unroll
        for (int s = 0; s < 4; s++) {
            uint32_t afr[2][4];
#pragma unroll
            for (int mi = 0; mi < 2; mi++)
                ldsm_x4(afr[mi], As_b + ((lrow + mi * 16) * 36 + s * 8 + lcol) * 4);
#pragma unroll
            for (int j = 0; j < 12; j++) {
                int col = wc * 96 + j * 8 + g;
                uint32_t b0 = Bs[s * 8 + t][col];
                uint32_t b1 = Bs[s * 8 + t + 4][col];
                mma_tf32(c[0][j], afr[0], b0, b1);
                mma_tf32(c[1][j], afr[1], b0, b1);
            }
        }
    }

#pragma unroll
    for (int mi = 0; mi < 2; mi++) {
        int rb = row0 + wr * 32 + mi * 16;
#pragma unroll
        for (int j = 0; j < 12; j++) {
            int cb = wc * 96 + j * 8;
            int seg = cb >> 6;
            int off = (cb & 63) + 2 * t;
            float* base = (seg == 0) ? g_q : (seg == 1) ? g_k : g_v;
            float2 v0; v0.x = c[mi][j][0]; v0.y = c[mi][j][1];
            float2 v1; v1.x = c[mi][j][2]; v1.y = c[mi][j][3];
            *(float2*)&base[(size_t)(rb + g) * 64 + off] = v0;
            *(float2*)&base[(size_t)(rb + g + 8) * 64 + off] = v1;
        }
    }
}

// ---------------------------------------------------------------------------
// Kernel 2: split-K flash attention, fully tensorized:
// S = QK^T via tf32 HMMA, PV via tf32 HMMA (P stored tf32 in smem, re-read
// via ldmatrix; A-rows are warp-private -> __syncwarp only; corr in regs).
// ks pitch 68 (bank 4gq+t distinct) and vs pitch 72 (bank 8t+gq distinct)
// make both B-operand patterns conflict-free.
// ---------------------------------------------------------------------------
__global__ __launch_bounds__(128) void attn_kernel(
    const float* __restrict__ rbias)
{
    __shared__ uint32_t qs[64][68];    // tf32 bits, [row][h]
    __shared__ uint32_t ks[32][68];    // tf32 bits, [key][h]
    __shared__ uint32_t vs[32][72];    // tf32 bits, [key][h]
    __shared__ uint32_t ss[64][36];    // tf32 p bits, [row][key-local]

    const int b = blockIdx.y;
    const int half = blockIdx.z;
    const int qb = 31 - blockIdx.x;      // heavy tiles first
    const int q0 = qb * 64;
    const int tid = threadIdx.x;
    const int w = tid >> 5;
    const int lane = tid & 31;
    const int gq = lane >> 2;            // 0..7
    const int t = lane & 3;              // 0..3

    // Load Q tile (64 x 64) -> qs tf32
#pragma unroll
    for (int i = 0; i < 8; i++) {
        int idx = tid + 128 * i;
        int r = idx >> 4, hs = (idx & 15) * 4;
        float4 v = *(const float4*)&g_q[((size_t)(b * TT + q0 + r)) * HH + hs];
        uint32_t* d = &qs[r][hs];
        d[0] = cvt_tf32(v.x); d[1] = cvt_tf32(v.y);
        d[2] = cvt_tf32(v.z); d[3] = cvt_tf32(v.w);
    }
    __syncthreads();

    const uint32_t lrow = w * 16 + (lane & 15);
    const uint32_t lcol = (lane >> 4) * 4;

    // Preload Q fragments for all 8 k8-steps
    uint32_t qfr[8][4];
    {
        const uint32_t qs_b = smem_u32(&qs[0][0]);
#pragma unroll
        for (int s = 0; s < 8; s++)
            ldsm_x4(qfr[s], qs_b + (lrow * 68 + s * 8 + lcol) * 4);
    }
    const uint32_t ss_b = smem_u32(&ss[0][0]);

    const int rA = w * 16 + gq;
    const int rB = rA + 8;
    const int qiA = q0 + rA, qiB = q0 + rB;
    float m0 = -1e30f, m1 = -1e30f, l0 = 0.f, l1 = 0.f;

    float opv[8][4];                     // PV accum: 8 n8-frags (h = 0..63)
#pragma unroll
    for (int j = 0; j < 8; j++)
#pragma unroll
        for (int q = 0; q < 4; q++) opv[j][q] = 0.f;

    const int nkb = 2 * qb + 2;          // 32-key tiles covering [0, q0+64)
    const int kb_beg = half ? nkb / 2 : 0;
    const int kb_end = half ? nkb : nkb / 2;

    for (int kb = kb_beg; kb < kb_end; kb++) {
        const int k0 = kb * 32;
        __syncthreads();   // previous PV B-reads of vs done

        // Load K, V tiles (tf32), [key][h]
#pragma unroll
        for (int i = 0; i < 4; i++) {
            int idx = tid + 128 * i;
            int r = idx >> 4, hs = (idx & 15) * 4;
            size_t gi = ((size_t)(b * TT + k0 + r)) * HH + hs;
            float4 kv = *(const float4*)&g_k[gi];
            uint32_t* kd = &ks[r][hs];
            kd[0] = cvt_tf32(kv.x); kd[1] = cvt_tf32(kv.y);
            kd[2] = cvt_tf32(kv.z); kd[3] = cvt_tf32(kv.w);
            float4 vv = *(const float4*)&g_v[gi];
            uint32_t* vd = &vs[r][hs];
            vd[0] = cvt_tf32(vv.x); vd[1] = cvt_tf32(vv.y);
            vd[2] = cvt_tf32(vv.z); vd[3] = cvt_tf32(vv.w);
        }
        __syncthreads();

        // S = Q K^T : per warp m16 x n32 (4 n8 frags), 8 k8 steps
        float c[4][4];
#pragma unroll
        for (int j = 0; j < 4; j++)
#pragma unroll
            for (int q = 0; q < 4; q++) c[j][q] = 0.f;
#pragma unroll
        for (int s = 0; s < 8; s++) {
#pragma unroll
            for (int j = 0; j < 4; j++) {
                uint32_t b0 = ks[j * 8 + gq][s * 8 + t];
                uint32_t b1 = ks[j * 8 + gq][s * 8 + t + 4];
                mma_tf32(c[j], qfr[s], b0, b1);
            }
        }

        // Softmax epilogue in fragment layout
        float sA[8], sB[8];
        float mxA = -1e30f, mxB = -1e30f;
#pragma unroll
        for (int j = 0; j < 4; j++) {
            int kj = k0 + j * 8 + 2 * t;
            float2 ba = *(const float2*)&rbias[(size_t)qiA * TT + kj];
            float2 bbv = *(const float2*)&rbias[(size_t)qiB * TT + kj];
            bool a0 = (kj <= qiA) && (ba.x > 0.f || kj == qiA);
            bool a1 = (kj + 1 <= qiA) && (ba.y > 0.f || kj + 1 == qiA);
            bool b0k = (kj <= qiB) && (bbv.x > 0.f || kj == qiB);
            bool b1k = (kj + 1 <= qiB) && (bbv.y > 0.f || kj + 1 == qiB);
            sA[2 * j]     = a0 ? fmaf(c[j][0], 0.03125f, ba.x) : -1e30f;
            sA[2 * j + 1] = a1 ? fmaf(c[j][1], 0.03125f, ba.y) : -1e30f;
            sB[2 * j]     = b0k ? fmaf(c[j][2], 0.03125f, bbv.x) : -1e30f;
            sB[2 * j + 1] = b1k ? fmaf(c[j][3], 0.03125f, bbv.y) : -1e30f;
            mxA = fmaxf(mxA, fmaxf(sA[2 * j], sA[2 * j + 1]));
            mxB = fmaxf(mxB, fmaxf(sB[2 * j], sB[2 * j + 1]));
        }
        mxA = fmaxf(mxA, __shfl_xor_sync(0xffffffffu, mxA, 1));
        mxA = fmaxf(mxA, __shfl_xor_sync(0xffffffffu, mxA, 2));
        mxB = fmaxf(mxB, __shfl_xor_sync(0xffffffffu, mxB, 1));
        mxB = fmaxf(mxB, __shfl_xor_sync(0xffffffffu, mxB, 2));

        float mA = fmaxf(m0, mxA), mB = fmaxf(m1, mxB);
        float baseA = fmaxf(mA, -1e28f), baseB = fmaxf(mB, -1e28f);
        float crA = __expf(m0 - mA), crB = __expf(m1 - mB);
        m0 = mA; m1 = mB;
        float sumA = 0.f, sumB = 0.f;
#pragma unroll
        for (int jj = 0; jj < 8; jj++) {
            float pA = __expf(sA[jj] - baseA);
            float pB = __expf(sB[jj] - baseB);
            sumA += pA; sumB += pB;
            sA[jj] = pA; sB[jj] = pB;
        }
        // store P (tf32 bits) to warp-private ss rows
#pragma unroll
        for (int j = 0; j < 4; j++) {
            uint2 wa; wa.x = cvt_tf32(sA[2 * j]); wa.y = cvt_tf32(sA[2 * j + 1]);
            uint2 wb; wb.x = cvt_tf32(sB[2 * j]); wb.y = cvt_tf32(sB[2 * j + 1]);
            *(uint2*)&ss[rA][j * 8 + 2 * t] = wa;
            *(uint2*)&ss[rB][j * 8 + 2 * t] = wb;
        }
        sumA += __shfl_xor_sync(0xffffffffu, sumA, 1);
        sumA += __shfl_xor_sync(0xffffffffu, sumA, 2);
        sumB += __shfl_xor_sync(0xffffffffu, sumB, 1);
        sumB += __shfl_xor_sync(0xffffffffu, sumB, 2);
        l0 = l0 * crA + sumA;
        l1 = l1 * crB + sumB;
        __syncwarp();

        // rescale O by corr (rows gq -> crA, gq+8 -> crB)
#pragma unroll
        for (int j = 0; j < 8; j++) {
            opv[j][0] *= crA; opv[j][1] *= crA;
            opv[j][2] *= crB; opv[j][3] *= crB;
        }

        // PV: A = P (ldmatrix from ss, warp-private rows), B = V
#pragma unroll
        for (int s = 0; s < 4; s++) {
            uint32_t pfr[4];
            ldsm_x4(pfr, ss_b + (lrow * 36 + s * 8 + lcol) * 4);
#pragma unroll
            for (int j = 0; j < 8; j++) {
                uint32_t b0 = vs[s * 8 + t][j * 8 + gq];
                uint32_t b1 = vs[s * 8 + t + 4][j * 8 + gq];
                mma_tf32(opv[j], pfr, b0, b1);
            }
        }
    }

    // epilogue: write unnormalized partials + (m, l)
    const size_t hoff = (size_t)half * (BB * TT * HH);
    const size_t rowA = (size_t)(b * TT) + qiA;
    const size_t rowB = (size_t)(b * TT) + qiB;
#pragma unroll
    for (int j = 0; j < 8; j++) {
        int col = j * 8 + 2 * t;
        float2 va; va.x = opv[j][0]; va.y = opv[j][1];
        float2 vb; vb.x = opv[j][2]; vb.y = opv[j][3];
        *(float2*)&g_po[hoff + rowA * HH + col] = va;
        *(float2*)&g_po[hoff + rowB * HH + col] = vb;
    }
    if (t == 0) {
        g_pm[half * (BB * TT) + rowA] = m0;
        g_pl[half * (BB * TT) + rowA] = l0;
        g_pm[half * (BB * TT) + rowB] = m1;
        g_pl[half * (BB * TT) + rowB] = l1;
    }
}

// ---------------------------------------------------------------------------
// Kernel 3: merge split-K halves and normalize.
// ---------------------------------------------------------------------------
__global__ __launch_bounds__(256) void combine_kernel(float* __restrict__ out)
{
    int idx = blockIdx.x * 256 + threadIdx.x;
    int e = idx * 4;
    int row = e >> 6;
    float m0 = g_pm[row], m1 = g_pm[BB * TT + row];
    float l0 = g_pl[row], l1 = g_pl[BB * TT + row];
    float mm = fmaxf(m0, m1);
    float a0 = __expf(m0 - mm);
    float a1 = __expf(m1 - mm);
    float inv = 1.f / (l0 * a0 + l1 * a1);
    float4 x0 = *(const float4*)&g_po[e];
    float4 x1 = *(const float4*)&g_po[BB * TT * HH + e];
    float4 r;
    r.x = (x0.x * a0 + x1.x * a1) * inv;
    r.y = (x0.y * a0 + x1.y * a1) * inv;
    r.z = (x0.z * a0 + x1.z * a1) * inv;
    r.w = (x0.w * a0 + x1.w * a1) * inv;
    *(float4*)&out[e] = r;
}

// ---------------------------------------------------------------------------
// Inputs (metadata order): x, Wq, Wk, Wv, rbias, allowed
// Output: [B, T, H] float32
// ---------------------------------------------------------------------------
extern "C" void kernel_launch(void* const* d_in, const int* in_sizes, int n_in,
                              void* d_out, int out_size)
{
    const float* x     = (const float*)d_in[0];
    const float* Wq    = (const float*)d_in[1];
    const float* Wk    = (const float*)d_in[2];
    const float* Wv    = (const float*)d_in[3];
    const float* rbias = (const float*)d_in[4];
    float* out = (float*)d_out;

    proj_kernel<<<128, 256>>>(x, Wq, Wk, Wv);
    attn_kernel<<<dim3(32, 8, 2), 128>>>(rbias);
    combine_kernel<<<1024, 256>>>(out);
}

// round 16
// speedup vs baseline: 5.3798x; 1.1007x over previous
#include <cuda_runtime.h>
#include <cstdint>

#define TT 2048
#define BB 8
#define CC 1024
#define HH 64

typedef unsigned long long u64;

__device__ __forceinline__ uint32_t cvt_tf32(float v) {
    uint32_t t; asm("cvt.rna.tf32.f32 %0, %1;" : "=r"(t) : "f"(v)); return t;
}
__device__ __forceinline__ uint32_t smem_u32(const void* p) {
    uint32_t a;
    asm("{ .reg .u64 t; cvta.to.shared.u64 t, %1; cvt.u32.u64 %0, t; }" : "=r"(a) : "l"(p));
    return a;
}
// HMMA tf32: D(16x8) += A(16x8) * B(8x8); base ISA (sm_80+).
__device__ __forceinline__ void mma_tf32(float* c, const uint32_t* a,
                                         uint32_t b0, uint32_t b1) {
    asm volatile(
        "mma.sync.aligned.m16n8k8.row.col.f32.tf32.tf32.f32 "
        "{%0,%1,%2,%3}, {%4,%5,%6,%7}, {%8,%9}, {%0,%1,%2,%3};"
        : "+f"(c[0]), "+f"(c[1]), "+f"(c[2]), "+f"(c[3])
        : "r"(a[0]), "r"(a[1]), "r"(a[2]), "r"(a[3]), "r"(b0), "r"(b1));
}
__device__ __forceinline__ void ldsm_x4(uint32_t* r, uint32_t addr) {
    asm volatile("ldmatrix.sync.aligned.m8n8.x4.shared.b16 {%0,%1,%2,%3}, [%4];"
                 : "=r"(r[0]), "=r"(r[1]), "=r"(r[2]), "=r"(r[3]) : "r"(addr));
}

// Scratch: projected q/k/v [B,T,H] fp32 + split-K partials.
__device__ float g_q[BB * TT * HH];
__device__ float g_k[BB * TT * HH];
__device__ float g_v[BB * TT * HH];
__device__ float g_po[2 * BB * TT * HH];
__device__ float g_pm[2 * BB * TT];
__device__ float g_pl[2 * BB * TT];

// ---------------------------------------------------------------------------
// Kernel 1: tf32 HMMA QKV projection, N-split.
// Grid 256 = 128 row-tiles x 2 col-halves of 96. CTA = 128 rows x 96 cols,
// 8 warps (warp tile 32 x 48 = 2 m16 x 6 n8), K chunks of 32, reg prefetch.
// ---------------------------------------------------------------------------
__global__ __launch_bounds__(256) void proj_kernel(
    const float* __restrict__ x,
    const float* __restrict__ Wq,
    const float* __restrict__ Wk,
    const float* __restrict__ Wv)
{
    __shared__ uint32_t As[128][36];   // [m][k], tf32 bits
    __shared__ uint32_t Bs[32][104];   // [k][n-local], tf32 bits (104%32=8 -> cf)

    const int tid = threadIdx.x;
    const int wid = tid >> 5;
    const int lane = tid & 31;
    const int g = lane >> 2;
    const int t = lane & 3;
    const int wr = wid & 3;            // 4 x 32 rows
    const int wc = wid >> 2;           // 2 x 48 cols
    const int row0 = (blockIdx.x >> 1) * 128;
    const int cs = (blockIdx.x & 1) * 96;   // column half base

    float c[2][6][4];
#pragma unroll
    for (int mi = 0; mi < 2; mi++)
#pragma unroll
        for (int j = 0; j < 6; j++)
#pragma unroll
            for (int q = 0; q < 4; q++) c[mi][j][q] = 0.f;

    // A fill: 4 float4/thread over 128x32
    const int ar = tid >> 3;                // 0..31 (+32*i)
    const int ac = (tid & 7) * 4;
    // B fill: 3 float4/thread over 32x96
    int br[3], bc[3];
    const float* wsrc[3];
#pragma unroll
    for (int i = 0; i < 3; i++) {
        int idx = tid + 256 * i;            // < 768
        br[i] = idx / 24;
        bc[i] = (idx - br[i] * 24) * 4;     // 0..92 local
        int gcol = cs + bc[i];
        int sgm = gcol >> 6;
        const float* W = (sgm == 0) ? Wq : (sgm == 1) ? Wk : Wv;
        wsrc[i] = W + (gcol & 63);
    }

    float4 pa[4], pb[3];
#pragma unroll
    for (int i = 0; i < 4; i++)
        pa[i] = *(const float4*)&x[(size_t)(row0 + ar + 32 * i) * CC + ac];
#pragma unroll
    for (int i = 0; i < 3; i++)
        pb[i] = *(const float4*)(wsrc[i] + (size_t)br[i] * 64);

    const uint32_t As_b = smem_u32(&As[0][0]);
    const uint32_t lrow = wr * 32 + (lane & 15);
    const uint32_t lcol = (lane >> 4) * 4;

    for (int kc = 0; kc < 32; kc++) {
        if (kc) __syncthreads();

#pragma unroll
        for (int i = 0; i < 4; i++) {
            uint32_t* d = &As[ar + 32 * i][ac];
            d[0] = cvt_tf32(pa[i].x); d[1] = cvt_tf32(pa[i].y);
            d[2] = cvt_tf32(pa[i].z); d[3] = cvt_tf32(pa[i].w);
        }
#pragma unroll
        for (int i = 0; i < 3; i++) {
            uint32_t* d = &Bs[br[i]][bc[i]];
            d[0] = cvt_tf32(pb[i].x); d[1] = cvt_tf32(pb[i].y);
            d[2] = cvt_tf32(pb[i].z); d[3] = cvt_tf32(pb[i].w);
        }
        __syncthreads();

        if (kc + 1 < 32) {
            const int k1 = (kc + 1) * 32;
#pragma unroll
            for (int i = 0; i < 4; i++)
                pa[i] = *(const float4*)&x[(size_t)(row0 + ar + 32 * i) * CC + k1 + ac];
#pragma unroll
            for (int i = 0; i < 3; i++)
                pb[i] = *(const float4*)(wsrc[i] + (size_t)(k1 + br[i]) * 64);
        }

#pragma unroll
        for (int s = 0; s < 4; s++) {
            uint32_t afr[2][4];
#pragma unroll
            for (int mi = 0; mi < 2; mi++)
                ldsm_x4(afr[mi], As_b + ((lrow + mi * 16) * 36 + s * 8 + lcol) * 4);
#pragma unroll
            for (int j = 0; j < 6; j++) {
                int col = wc * 48 + j * 8 + g;
                uint32_t b0 = Bs[s * 8 + t][col];
                uint32_t b1 = Bs[s * 8 + t + 4][col];
                mma_tf32(c[0][j], afr[0], b0, b1);
                mma_tf32(c[1][j], afr[1], b0, b1);
            }
        }
    }

#pragma unroll
    for (int mi = 0; mi < 2; mi++) {
        int rb = row0 + wr * 32 + mi * 16;
#pragma unroll
        for (int j = 0; j < 6; j++) {
            int cb = cs + wc * 48 + j * 8;
            int seg = cb >> 6;
            int off = (cb & 63) + 2 * t;
            float* base = (seg == 0) ? g_q : (seg == 1) ? g_k : g_v;
            float2 v0; v0.x = c[mi][j][0]; v0.y = c[mi][j][1];
            float2 v1; v1.x = c[mi][j][2]; v1.y = c[mi][j][3];
            *(float2*)&base[(size_t)(rb + g) * 64 + off] = v0;
            *(float2*)&base[(size_t)(rb + g + 8) * 64 + off] = v1;
        }
    }
}

// ---------------------------------------------------------------------------
// Kernel 2: split-K flash attention, fully tensorized, with register
// prefetch of K/V (gmem latency hidden behind compute) and rbias prefetch.
// ---------------------------------------------------------------------------
__global__ __launch_bounds__(128) void attn_kernel(
    const float* __restrict__ rbias)
{
    __shared__ uint32_t qs[64][68];    // tf32 bits, [row][h]
    __shared__ uint32_t ks[32][68];    // tf32 bits, [key][h]
    __shared__ uint32_t vs[32][72];    // tf32 bits, [key][h]
    __shared__ uint32_t ss[64][36];    // tf32 p bits, [row][key-local]

    const int b = blockIdx.y;
    const int half = blockIdx.z;
    const int qb = 31 - blockIdx.x;      // heavy tiles first
    const int q0 = qb * 64;
    const int tid = threadIdx.x;
    const int w = tid >> 5;
    const int lane = tid & 31;
    const int gq = lane >> 2;            // 0..7
    const int t = lane & 3;              // 0..3

    // Load Q tile (64 x 64) -> qs tf32
#pragma unroll
    for (int i = 0; i < 8; i++) {
        int idx = tid + 128 * i;
        int r = idx >> 4, hs = (idx & 15) * 4;
        float4 v = *(const float4*)&g_q[((size_t)(b * TT + q0 + r)) * HH + hs];
        uint32_t* d = &qs[r][hs];
        d[0] = cvt_tf32(v.x); d[1] = cvt_tf32(v.y);
        d[2] = cvt_tf32(v.z); d[3] = cvt_tf32(v.w);
    }
    __syncthreads();

    const uint32_t lrow = w * 16 + (lane & 15);
    const uint32_t lcol = (lane >> 4) * 4;

    // Preload Q fragments for all 8 k8-steps
    uint32_t qfr[8][4];
    {
        const uint32_t qs_b = smem_u32(&qs[0][0]);
#pragma unroll
        for (int s = 0; s < 8; s++)
            ldsm_x4(qfr[s], qs_b + (lrow * 68 + s * 8 + lcol) * 4);
    }
    const uint32_t ss_b = smem_u32(&ss[0][0]);

    const int rA = w * 16 + gq;
    const int rB = rA + 8;
    const int qiA = q0 + rA, qiB = q0 + rB;
    float m0 = -1e30f, m1 = -1e30f, l0 = 0.f, l1 = 0.f;

    float opv[8][4];
#pragma unroll
    for (int j = 0; j < 8; j++)
#pragma unroll
        for (int q = 0; q < 4; q++) opv[j][q] = 0.f;

    const int nkb = 2 * qb + 2;
    const int kb_beg = half ? nkb / 2 : 0;
    const int kb_end = half ? nkb : nkb / 2;

    // per-thread K/V load coordinates (fixed)
    int ldr[4], ldh[4];
#pragma unroll
    for (int i = 0; i < 4; i++) {
        int idx = tid + 128 * i;
        ldr[i] = idx >> 4;
        ldh[i] = (idx & 15) * 4;
    }

    // prefetch first tile into registers
    float4 pk[4], pv[4];
    {
        const int k0 = kb_beg * 32;
#pragma unroll
        for (int i = 0; i < 4; i++) {
            size_t gi = ((size_t)(b * TT + k0 + ldr[i])) * HH + ldh[i];
            pk[i] = *(const float4*)&g_k[gi];
            pv[i] = *(const float4*)&g_v[gi];
        }
    }

    for (int kb = kb_beg; kb < kb_end; kb++) {
        const int k0 = kb * 32;
        __syncthreads();   // previous S/PV reads of ks/vs done

        // store prefetched K/V (cvt to tf32)
#pragma unroll
        for (int i = 0; i < 4; i++) {
            uint32_t* kd = &ks[ldr[i]][ldh[i]];
            kd[0] = cvt_tf32(pk[i].x); kd[1] = cvt_tf32(pk[i].y);
            kd[2] = cvt_tf32(pk[i].z); kd[3] = cvt_tf32(pk[i].w);
            uint32_t* vd = &vs[ldr[i]][ldh[i]];
            vd[0] = cvt_tf32(pv[i].x); vd[1] = cvt_tf32(pv[i].y);
            vd[2] = cvt_tf32(pv[i].z); vd[3] = cvt_tf32(pv[i].w);
        }
        __syncthreads();

        // prefetch next tile (LDGs in flight during compute)
        if (kb + 1 < kb_end) {
            const int k1 = k0 + 32;
#pragma unroll
            for (int i = 0; i < 4; i++) {
                size_t gi = ((size_t)(b * TT + k1 + ldr[i])) * HH + ldh[i];
                pk[i] = *(const float4*)&g_k[gi];
                pv[i] = *(const float4*)&g_v[gi];
            }
        }

        // rbias prefetch (epilogue operands, L2-latency hidden behind MMA)
        float2 rba[4], rbb[4];
#pragma unroll
        for (int j = 0; j < 4; j++) {
            int kj = k0 + j * 8 + 2 * t;
            rba[j] = *(const float2*)&rbias[(size_t)qiA * TT + kj];
            rbb[j] = *(const float2*)&rbias[(size_t)qiB * TT + kj];
        }

        // S = Q K^T : per warp m16 x n32, 8 k8 steps
        float c[4][4];
#pragma unroll
        for (int j = 0; j < 4; j++)
#pragma unroll
            for (int q = 0; q < 4; q++) c[j][q] = 0.f;
#pragma unroll
        for (int s = 0; s < 8; s++) {
#pragma unroll
            for (int j = 0; j < 4; j++) {
                uint32_t b0 = ks[j * 8 + gq][s * 8 + t];
                uint32_t b1 = ks[j * 8 + gq][s * 8 + t + 4];
                mma_tf32(c[j], qfr[s], b0, b1);
            }
        }

        // Softmax epilogue in fragment layout
        float sA[8], sB[8];
        float mxA = -1e30f, mxB = -1e30f;
#pragma unroll
        for (int j = 0; j < 4; j++) {
            int kj = k0 + j * 8 + 2 * t;
            bool a0 = (kj <= qiA) && (rba[j].x > 0.f || kj == qiA);
            bool a1 = (kj + 1 <= qiA) && (rba[j].y > 0.f || kj + 1 == qiA);
            bool b0k = (kj <= qiB) && (rbb[j].x > 0.f || kj == qiB);
            bool b1k = (kj + 1 <= qiB) && (rbb[j].y > 0.f || kj + 1 == qiB);
            sA[2 * j]     = a0 ? fmaf(c[j][0], 0.03125f, rba[j].x) : -1e30f;
            sA[2 * j + 1] = a1 ? fmaf(c[j][1], 0.03125f, rba[j].y) : -1e30f;
            sB[2 * j]     = b0k ? fmaf(c[j][2], 0.03125f, rbb[j].x) : -1e30f;
            sB[2 * j + 1] = b1k ? fmaf(c[j][3], 0.03125f, rbb[j].y) : -1e30f;
            mxA = fmaxf(mxA, fmaxf(sA[2 * j], sA[2 * j + 1]));
            mxB = fmaxf(mxB, fmaxf(sB[2 * j], sB[2 * j + 1]));
        }
        mxA = fmaxf(mxA, __shfl_xor_sync(0xffffffffu, mxA, 1));
        mxA = fmaxf(mxA, __shfl_xor_sync(0xffffffffu, mxA, 2));
        mxB = fmaxf(mxB, __shfl_xor_sync(0xffffffffu, mxB, 1));
        mxB = fmaxf(mxB, __shfl_xor_sync(0xffffffffu, mxB, 2));

        float mA = fmaxf(m0, mxA), mB = fmaxf(m1, mxB);
        float baseA = fmaxf(mA, -1e28f), baseB = fmaxf(mB, -1e28f);
        float crA = __expf(m0 - mA), crB = __expf(m1 - mB);
        m0 = mA; m1 = mB;
        float sumA = 0.f, sumB = 0.f;
#pragma unroll
        for (int jj = 0; jj < 8; jj++) {
            float pA = __expf(sA[jj] - baseA);
            float pB = __expf(sB[jj] - baseB);
            sumA += pA; sumB += pB;
            sA[jj] = pA; sB[jj] = pB;
        }
#pragma unroll
        for (int j = 0; j < 4; j++) {
            uint2 wa; wa.x = cvt_tf32(sA[2 * j]); wa.y = cvt_tf32(sA[2 * j + 1]);
            uint2 wb; wb.x = cvt_tf32(sB[2 * j]); wb.y = cvt_tf32(sB[2 * j + 1]);
            *(uint2*)&ss[rA][j * 8 + 2 * t] = wa;
            *(uint2*)&ss[rB][j * 8 + 2 * t] = wb;
        }
        sumA += __shfl_xor_sync(0xffffffffu, sumA, 1);
        sumA += __shfl_xor_sync(0xffffffffu, sumA, 2);
        sumB += __shfl_xor_sync(0xffffffffu, sumB, 1);
        sumB += __shfl_xor_sync(0xffffffffu, sumB, 2);
        l0 = l0 * crA + sumA;
        l1 = l1 * crB + sumB;
        __syncwarp();

        // rescale O by corr
#pragma unroll
        for (int j = 0; j < 8; j++) {
            opv[j][0] *= crA; opv[j][1] *= crA;
            opv[j][2] *= crB; opv[j][3] *= crB;
        }

        // PV: A = P (ldmatrix, warp-private rows), B = V
#pragma unroll
        for (int s = 0; s < 4; s++) {
            uint32_t pfr[4];
            ldsm_x4(pfr, ss_b + (lrow * 36 + s * 8 + lcol) * 4);
#pragma unroll
            for (int j = 0; j < 8; j++) {
                uint32_t b0 = vs[s * 8 + t][j * 8 + gq];
                uint32_t b1 = vs[s * 8 + t + 4][j * 8 + gq];
                mma_tf32(opv[j], pfr, b0, b1);
            }
        }
    }

    // epilogue: write unnormalized partials + (m, l)
    const size_t hoff = (size_t)half * (BB * TT * HH);
    const size_t rowA = (size_t)(b * TT) + qiA;
    const size_t rowB = (size_t)(b * TT) + qiB;
#pragma unroll
    for (int j = 0; j < 8; j++) {
        int col = j * 8 + 2 * t;
        float2 va; va.x = opv[j][0]; va.y = opv[j][1];
        float2 vb; vb.x = opv[j][2]; vb.y = opv[j][3];
        *(float2*)&g_po[hoff + rowA * HH + col] = va;
        *(float2*)&g_po[hoff + rowB * HH + col] = vb;
    }
    if (t == 0) {
        g_pm[half * (BB * TT) + rowA] = m0;
        g_pl[half * (BB * TT) + rowA] = l0;
        g_pm[half * (BB * TT) + rowB] = m1;
        g_pl[half * (BB * TT) + rowB] = l1;
    }
}

// ---------------------------------------------------------------------------
// Kernel 3: merge split-K halves and normalize.
// ---------------------------------------------------------------------------
__global__ __launch_bounds__(256) void combine_kernel(float* __restrict__ out)
{
    int idx = blockIdx.x * 256 + threadIdx.x;
    int e = idx * 4;
    int row = e >> 6;
    float m0 = g_pm[row], m1 = g_pm[BB * TT + row];
    float l0 = g_pl[row], l1 = g_pl[BB * TT + row];
    float mm = fmaxf(m0, m1);
    float a0 = __expf(m0 - mm);
    float a1 = __expf(m1 - mm);
    float inv = 1.f / (l0 * a0 + l1 * a1);
    float4 x0 = *(const float4*)&g_po[e];
    float4 x1 = *(const float4*)&g_po[BB * TT * HH + e];
    float4 r;
    r.x = (x0.x * a0 + x1.x * a1) * inv;
    r.y = (x0.y * a0 + x1.y * a1) * inv;
    r.z = (x0.z * a0 + x1.z * a1) * inv;
    r.w = (x0.w * a0 + x1.w * a1) * inv;
    *(float4*)&out[e] = r;
}

// ---------------------------------------------------------------------------
// Inputs (metadata order): x, Wq, Wk, Wv, rbias, allowed
// Output: [B, T, H] float32
// ---------------------------------------------------------------------------
extern "C" void kernel_launch(void* const* d_in, const int* in_sizes, int n_in,
                              void* d_out, int out_size)
{
    const float* x     = (const float*)d_in[0];
    const float* Wq    = (const float*)d_in[1];
    const float* Wk    = (const float*)d_in[2];
    const float* Wv    = (const float*)d_in[3];
    const float* rbias = (const float*)d_in[4];
    float* out = (float*)d_out;

    proj_kernel<<<256, 256>>>(x, Wq, Wk, Wv);
    attn_kernel<<<dim3(32, 8, 2), 128>>>(rbias);
    combine_kernel<<<1024, 256>>>(out);
}